// round 1
// baseline (speedup 1.0000x reference)
#include <cuda_runtime.h>

#define NN 10000
#define NE 160000
#define HD 256

// ---------------- scratch (device globals; no allocations) ----------------
__device__ float g_PA [NN*HD];
__device__ float g_PB [NN*HD];
__device__ float g_PMX[NN*HD];
__device__ float g_XW [NN*HD];
__device__ float g_s  [NN*HD];
__device__ float g_cnt[NN];
__device__ float g_nh [NN*HD];
__device__ float g_x2 [NN*HD];
__device__ float g_eh [(size_t)NE*HD];   // eh0 -> eh1 -> h (reused)
__device__ float g_ea1[(size_t)NE*HD];
__device__ float g_ea2[(size_t)NE*HD];
__device__ int   g_src[NE];
__device__ int   g_dst[NE];

// ---------------- index conversion (auto-detect int64 vs int32) ----------------
__global__ void convert_idx(const unsigned int* __restrict__ raw) {
    __shared__ int s64;
    if (threadIdx.x == 0) {
        int ok = 1;
        for (int i = 1; i < 256; i += 2) {
            if (raw[i] != 0u) { ok = 0; break; }
        }
        s64 = ok;
    }
    __syncthreads();
    const int is64 = s64;
    int i = blockIdx.x * blockDim.x + threadIdx.x;
    if (i < NE) {
        if (is64) {
            g_src[i] = (int)raw[2 * (size_t)i];
            g_dst[i] = (int)raw[2 * ((size_t)NE + i)];
        } else {
            const int* r32 = (const int*)raw;
            g_src[i] = r32[i];
            g_dst[i] = r32[NE + i];
        }
    }
}

// ---------------- zero s and cnt ----------------
__global__ void zero_s_cnt() {
    size_t i = (size_t)blockIdx.x * blockDim.x + threadIdx.x;
    if (i < (size_t)NN * HD) g_s[i] = 0.f;
    if (i < NN) g_cnt[i] = 0.f;
}

// ---------------- in-degree counts ----------------
__global__ void deg_kernel() {
    int i = blockIdx.x * blockDim.x + threadIdx.x;
    if (i < NE) atomicAdd(&g_cnt[g_dst[i]], 1.0f);
}

// ---------------- layer-0 edge pre-activation assembly (K=6 part) ----------------
// eh0[e,n] = relu(PA[src[e],n] + PB[dst[e],n] + sum_k ea[e,k]*Wea[k,n] + b1[n])
__global__ __launch_bounds__(256) void assemble_eh0(
    const float* __restrict__ eattr,      // [NE,6]
    const float* __restrict__ Wea,        // [6,256]
    const float* __restrict__ b1)         // [256]
{
    __shared__ float Ws[6 * 256];
    __shared__ float bs[256];
    const int n = threadIdx.x;
    #pragma unroll
    for (int i = n; i < 6 * 256; i += 256) Ws[i] = Wea[i];
    bs[n] = b1[n];
    __syncthreads();

    const int e0 = blockIdx.x * 64;
    for (int e = e0; e < e0 + 64; ++e) {
        const int s = g_src[e], d = g_dst[e];
        const float* ar = eattr + (size_t)e * 6;
        float a0 = ar[0], a1 = ar[1], a2 = ar[2], a3 = ar[3], a4 = ar[4], a5 = ar[5];
        float t = bs[n] + g_PA[(size_t)s * HD + n] + g_PB[(size_t)d * HD + n];
        t += a0 * Ws[0 * 256 + n];
        t += a1 * Ws[1 * 256 + n];
        t += a2 * Ws[2 * 256 + n];
        t += a3 * Ws[3 * 256 + n];
        t += a4 * Ws[4 * 256 + n];
        t += a5 * Ws[5 * 256 + n];
        g_eh[(size_t)e * HD + n] = fmaxf(t, 0.f);
    }
}

// ---------------- generic SGEMM with fused epilogue ----------------
// C[m, 0:256] = epi( A[m,:K] @ W[:K, 0:256] )
// epi: *rowscale(cnt) -> +bias -> +G1[idx1[m]] -> +G2[idx2[m]] -> +R[m] -> relu
//      -> store C[m] (or atomicAdd into Cout[sidx[m]])
__global__ __launch_bounds__(256) void gemm_epi(
    const float* __restrict__ A, int M, int K,
    const float* __restrict__ W,
    const float* __restrict__ bias,
    const float* __restrict__ G1, const int* __restrict__ idx1,
    const float* __restrict__ G2, const int* __restrict__ idx2,
    const float* __restrict__ R,
    const float* __restrict__ cnt,
    int do_relu,
    float* __restrict__ Cout,
    const int* __restrict__ sidx)
{
    __shared__ float As[16][132];   // padded to avoid bank conflicts
    __shared__ float Bs[16][64];

    const int tid = threadIdx.x;
    const int bm = blockIdx.x * 128;
    const int bn = blockIdx.y * 64;
    const int tx = tid & 15;        // 16 col groups x 4 cols
    const int ty = tid >> 4;        // 16 row groups x 8 rows

    float acc[8][4];
    #pragma unroll
    for (int i = 0; i < 8; ++i)
        #pragma unroll
        for (int j = 0; j < 4; ++j) acc[i][j] = 0.f;

    for (int k0 = 0; k0 < K; k0 += 16) {
        // stage A tile 128x16 (transposed into smem)
        #pragma unroll
        for (int l = 0; l < 2; ++l) {
            int i = tid + l * 256;
            int r = i >> 2;
            int c4 = (i & 3) << 2;
            int row = bm + r;
            float4 v = make_float4(0.f, 0.f, 0.f, 0.f);
            if (row < M) v = *(const float4*)(A + (size_t)row * K + k0 + c4);
            As[c4 + 0][r] = v.x;
            As[c4 + 1][r] = v.y;
            As[c4 + 2][r] = v.z;
            As[c4 + 3][r] = v.w;
        }
        // stage W tile 16x64
        {
            int r = tid >> 4;
            int c4 = (tid & 15) << 2;
            *(float4*)&Bs[r][c4] = *(const float4*)(W + (size_t)(k0 + r) * HD + bn + c4);
        }
        __syncthreads();

        #pragma unroll
        for (int kk = 0; kk < 16; ++kk) {
            float4 a0 = *(const float4*)&As[kk][ty * 8];
            float4 a1 = *(const float4*)&As[kk][ty * 8 + 4];
            float4 b  = *(const float4*)&Bs[kk][tx * 4];
            float av[8] = {a0.x, a0.y, a0.z, a0.w, a1.x, a1.y, a1.z, a1.w};
            float bv[4] = {b.x, b.y, b.z, b.w};
            #pragma unroll
            for (int i = 0; i < 8; ++i)
                #pragma unroll
                for (int j = 0; j < 4; ++j)
                    acc[i][j] += av[i] * bv[j];
        }
        __syncthreads();
    }

    const int cols = bn + tx * 4;
    float4 bv4 = make_float4(0.f, 0.f, 0.f, 0.f);
    if (bias) bv4 = *(const float4*)(bias + cols);

    #pragma unroll
    for (int i = 0; i < 8; ++i) {
        int row = bm + ty * 8 + i;
        if (row >= M) continue;
        float rs = 1.f;
        if (cnt) rs = 1.f / fmaxf(cnt[row], 1.f);
        float c0 = acc[i][0] * rs + bv4.x;
        float c1 = acc[i][1] * rs + bv4.y;
        float c2 = acc[i][2] * rs + bv4.z;
        float c3 = acc[i][3] * rs + bv4.w;
        if (G1) {
            float4 g = *(const float4*)(G1 + (size_t)idx1[row] * HD + cols);
            c0 += g.x; c1 += g.y; c2 += g.z; c3 += g.w;
        }
        if (G2) {
            float4 g = *(const float4*)(G2 + (size_t)idx2[row] * HD + cols);
            c0 += g.x; c1 += g.y; c2 += g.z; c3 += g.w;
        }
        if (R) {
            float4 r4 = *(const float4*)(R + (size_t)row * HD + cols);
            c0 += r4.x; c1 += r4.y; c2 += r4.z; c3 += r4.w;
        }
        if (do_relu) {
            c0 = fmaxf(c0, 0.f); c1 = fmaxf(c1, 0.f);
            c2 = fmaxf(c2, 0.f); c3 = fmaxf(c3, 0.f);
        }
        if (sidx) {
            float* o = Cout + (size_t)sidx[row] * HD + cols;
            atomicAdd(o + 0, c0);
            atomicAdd(o + 1, c1);
            atomicAdd(o + 2, c2);
            atomicAdd(o + 3, c3);
        } else {
            *(float4*)(Cout + (size_t)row * HD + cols) = make_float4(c0, c1, c2, c3);
        }
    }
}

// ---------------- final head reduction: out[e] = h[e] . p_w2 + p_b2 ----------------
__global__ __launch_bounds__(256) void head_kernel(
    const float* __restrict__ w2, const float* __restrict__ b2,
    float* __restrict__ out)
{
    int g = blockIdx.x * blockDim.x + threadIdx.x;
    int e = g >> 5, lane = g & 31;
    if (e >= NE) return;
    const float* hr = g_eh + (size_t)e * HD;
    float acc = 0.f;
    #pragma unroll
    for (int n = lane; n < HD; n += 32) acc += hr[n] * w2[n];
    #pragma unroll
    for (int o = 16; o; o >>= 1) acc += __shfl_xor_sync(0xffffffffu, acc, o);
    if (lane == 0) out[e] = acc + b2[0];
}

// ---------------- host-side GEMM wrapper ----------------
static void gemm(const float* A, int M, int K, const float* W, const float* bias,
                 const float* G1, const int* i1, const float* G2, const int* i2,
                 const float* R, const float* cnt, int relu,
                 float* C, const int* sidx)
{
    dim3 grid((M + 127) / 128, HD / 64);
    gemm_epi<<<grid, 256>>>(A, M, K, W, bias, G1, i1, G2, i2, R, cnt, relu, C, sidx);
}

extern "C" void kernel_launch(void* const* d_in, const int* in_sizes, int n_in,
                              void* d_out, int out_size)
{
    const float* x      = (const float*)d_in[0];
    const unsigned int* ei = (const unsigned int*)d_in[1];
    const float* eattr  = (const float*)d_in[2];
    const float* e_w1_0 = (const float*)d_in[3];
    const float* e_b1_0 = (const float*)d_in[4];
    const float* e_w2_0 = (const float*)d_in[5];
    const float* e_b2_0 = (const float*)d_in[6];
    const float* n_wm_0 = (const float*)d_in[7];
    const float* n_bm_0 = (const float*)d_in[8];
    const float* n_w1_0 = (const float*)d_in[9];
    const float* n_b1_0 = (const float*)d_in[10];
    const float* n_w2_0 = (const float*)d_in[11];
    const float* n_b2_0 = (const float*)d_in[12];
    const float* e_w1_1 = (const float*)d_in[13];
    const float* e_b1_1 = (const float*)d_in[14];
    const float* e_w2_1 = (const float*)d_in[15];
    const float* e_b2_1 = (const float*)d_in[16];
    // d_in[17..22]: layer-1 node model weights — provably dead (output uses only ea2)
    const float* p_w1   = (const float*)d_in[23];
    const float* p_b1   = (const float*)d_in[24];
    const float* p_w2   = (const float*)d_in[25];
    const float* p_b2   = (const float*)d_in[26];
    float* out = (float*)d_out;

    float *PA, *PB, *PMX, *XW, *S, *CNT, *NH, *X2, *EH, *EA1, *EA2;
    int *SRC, *DST;
    cudaGetSymbolAddress((void**)&PA,  g_PA);
    cudaGetSymbolAddress((void**)&PB,  g_PB);
    cudaGetSymbolAddress((void**)&PMX, g_PMX);
    cudaGetSymbolAddress((void**)&XW,  g_XW);
    cudaGetSymbolAddress((void**)&S,   g_s);
    cudaGetSymbolAddress((void**)&CNT, g_cnt);
    cudaGetSymbolAddress((void**)&NH,  g_nh);
    cudaGetSymbolAddress((void**)&X2,  g_x2);
    cudaGetSymbolAddress((void**)&EH,  g_eh);
    cudaGetSymbolAddress((void**)&EA1, g_ea1);
    cudaGetSymbolAddress((void**)&EA2, g_ea2);
    cudaGetSymbolAddress((void**)&SRC, g_src);
    cudaGetSymbolAddress((void**)&DST, g_dst);

    // weight sub-blocks (concat factorization; all row-major with 256 cols)
    const float* Wxi0 = e_w1_0;                 // x_i part  [512,256]
    const float* Wxj0 = e_w1_0 + 512 * 256;     // x_j part  [512,256]
    const float* Wea0 = e_w1_0 + 1024 * 256;    // ea  part  [6,256]
    const float* Wmx0 = n_wm_0;                 // x_i part  [512,256]
    const float* Wme0 = n_wm_0 + 512 * 256;     // ea  part  [256,256]
    const float* W1x0 = n_w1_0;                 // x   part  [512,256]
    const float* W1s0 = n_w1_0 + 512 * 256;     // s   part  [256,256]
    const float* Wxi1 = e_w1_1;                 // [256,256]
    const float* Wxj1 = e_w1_1 + 256 * 256;     // [256,256]
    const float* Wea1 = e_w1_1 + 512 * 256;     // [256,256]

    // 1) indices + degree
    convert_idx<<<(NE + 255) / 256, 256>>>(ei);
    zero_s_cnt<<<(NN * HD + 255) / 256, 256>>>();
    deg_kernel<<<(NE + 255) / 256, 256>>>();

    // 2) node-level projections for layer 0
    gemm(x, NN, 512, Wxi0, nullptr, nullptr, nullptr, nullptr, nullptr, nullptr, nullptr, 0, PA,  nullptr);
    gemm(x, NN, 512, Wxj0, nullptr, nullptr, nullptr, nullptr, nullptr, nullptr, nullptr, 0, PB,  nullptr);
    gemm(x, NN, 512, Wmx0, nullptr, nullptr, nullptr, nullptr, nullptr, nullptr, nullptr, 0, PMX, nullptr);
    gemm(x, NN, 512, W1x0, nullptr, nullptr, nullptr, nullptr, nullptr, nullptr, nullptr, 0, XW,  nullptr);

    // 3) eh0 = relu(PA[src] + PB[dst] + ea@Wea0 + e_b1_0)
    assemble_eh0<<<NE / 64, 256>>>(eattr, Wea0, e_b1_0);

    // 4) ea1 = eh0 @ e_w2_0 + e_b2_0
    gemm(EH, NE, 256, e_w2_0, e_b2_0, nullptr, nullptr, nullptr, nullptr, nullptr, nullptr, 0, EA1, nullptr);

    // 5) msg0 = relu(PMX[src] + ea1@Wme0 + n_bm_0); scatter-add into s[dst]
    gemm(EA1, NE, 256, Wme0, n_bm_0, PMX, SRC, nullptr, nullptr, nullptr, nullptr, 1, S, DST);

    // 6) nh0 = relu((s/max(cnt,1))@W1s0 + XW + n_b1_0)   (mean folded as rowscale)
    gemm(S, NN, 256, W1s0, n_b1_0, nullptr, nullptr, nullptr, nullptr, XW, CNT, 1, NH, nullptr);

    // 7) x2 = nh0 @ n_w2_0 + n_b2_0
    gemm(NH, NN, 256, n_w2_0, n_b2_0, nullptr, nullptr, nullptr, nullptr, nullptr, nullptr, 0, X2, nullptr);

    // 8) node-level projections for layer-1 edge model (reuse PA/PB)
    gemm(X2, NN, 256, Wxi1, nullptr, nullptr, nullptr, nullptr, nullptr, nullptr, nullptr, 0, PA, nullptr);
    gemm(X2, NN, 256, Wxj1, nullptr, nullptr, nullptr, nullptr, nullptr, nullptr, nullptr, 0, PB, nullptr);

    // 9) eh1 = relu(ea1@Wea1 + e_b1_1 + PA[src] + PB[dst])    (reuse EH)
    gemm(EA1, NE, 256, Wea1, e_b1_1, PA, SRC, PB, DST, nullptr, nullptr, 1, EH, nullptr);

    // 10) ea2 = eh1 @ e_w2_1 + e_b2_1 + ea1   (residual)
    gemm(EH, NE, 256, e_w2_1, e_b2_1, nullptr, nullptr, nullptr, nullptr, EA1, nullptr, 0, EA2, nullptr);

    // 11) h = relu(ea2 @ p_w1 + p_b1)          (reuse EH)
    gemm(EA2, NE, 256, p_w1, p_b1, nullptr, nullptr, nullptr, nullptr, nullptr, nullptr, 1, EH, nullptr);

    // 12) out[e] = h[e] . p_w2 + p_b2
    head_kernel<<<(NE * 32 + 255) / 256, 256>>>(p_w2, p_b2, out);

    (void)in_sizes; (void)n_in; (void)out_size;
}

// round 2
// speedup vs baseline: 1.0002x; 1.0002x over previous
#include <cuda_runtime.h>

#define NN 10000
#define NE 160000
#define HD 256

// ---------------- scratch (device globals; no allocations) ----------------
__device__ float g_PA [NN*HD];
__device__ float g_PB [NN*HD];
__device__ float g_PMX[NN*HD];
__device__ float g_XW [NN*HD];
__device__ float g_s  [NN*HD];
__device__ float g_cnt[NN];
__device__ float g_nh [NN*HD];
__device__ float g_x2 [NN*HD];
__device__ float g_eh [(size_t)NE*HD];   // eh0 -> eh1 -> h (reused)
__device__ float g_ea1[(size_t)NE*HD];
__device__ float g_ea2[(size_t)NE*HD];
__device__ int   g_src[NE];
__device__ int   g_dst[NE];

// ---------------- index conversion (auto-detect int64 vs int32) ----------------
__global__ void convert_idx(const unsigned int* __restrict__ raw) {
    __shared__ int s64;
    if (threadIdx.x == 0) {
        int ok = 1;
        for (int i = 1; i < 256; i += 2) {
            if (raw[i] != 0u) { ok = 0; break; }
        }
        s64 = ok;
    }
    __syncthreads();
    const int is64 = s64;
    int i = blockIdx.x * blockDim.x + threadIdx.x;
    if (i < NE) {
        if (is64) {
            g_src[i] = (int)raw[2 * (size_t)i];
            g_dst[i] = (int)raw[2 * ((size_t)NE + i)];
        } else {
            const int* r32 = (const int*)raw;
            g_src[i] = r32[i];
            g_dst[i] = r32[NE + i];
        }
    }
}

// ---------------- zero s and cnt ----------------
__global__ void zero_s_cnt() {
    size_t i = (size_t)blockIdx.x * blockDim.x + threadIdx.x;
    if (i < (size_t)NN * HD) g_s[i] = 0.f;
    if (i < NN) g_cnt[i] = 0.f;
}

// ---------------- in-degree counts ----------------
__global__ void deg_kernel() {
    int i = blockIdx.x * blockDim.x + threadIdx.x;
    if (i < NE) atomicAdd(&g_cnt[g_dst[i]], 1.0f);
}

// ---------------- layer-0 edge pre-activation assembly (K=6 part) ----------------
// eh0[e,n] = relu(PA[src[e],n] + PB[dst[e],n] + sum_k ea[e,k]*Wea[k,n] + b1[n])
__global__ __launch_bounds__(256) void assemble_eh0(
    const float* __restrict__ eattr,      // [NE,6]
    const float* __restrict__ Wea,        // [6,256]
    const float* __restrict__ b1)         // [256]
{
    __shared__ float Ws[6 * 256];
    __shared__ float bs[256];
    const int n = threadIdx.x;
    #pragma unroll
    for (int i = n; i < 6 * 256; i += 256) Ws[i] = Wea[i];
    bs[n] = b1[n];
    __syncthreads();

    const int e0 = blockIdx.x * 64;
    for (int e = e0; e < e0 + 64; ++e) {
        const int s = g_src[e], d = g_dst[e];
        const float* ar = eattr + (size_t)e * 6;
        float a0 = ar[0], a1 = ar[1], a2 = ar[2], a3 = ar[3], a4 = ar[4], a5 = ar[5];
        float t = bs[n] + g_PA[(size_t)s * HD + n] + g_PB[(size_t)d * HD + n];
        t += a0 * Ws[0 * 256 + n];
        t += a1 * Ws[1 * 256 + n];
        t += a2 * Ws[2 * 256 + n];
        t += a3 * Ws[3 * 256 + n];
        t += a4 * Ws[4 * 256 + n];
        t += a5 * Ws[5 * 256 + n];
        g_eh[(size_t)e * HD + n] = fmaxf(t, 0.f);
    }
}

// ---------------- generic SGEMM with fused epilogue ----------------
// C[m, 0:256] = epi( A[m,:K] @ W[:K, 0:256] )
// epi: *rowscale(cnt) -> +bias -> +G1[idx1[m]] -> +G2[idx2[m]] -> +R[m] -> relu
//      -> store C[m] (or atomicAdd into Cout[sidx[m]])
__global__ __launch_bounds__(256) void gemm_epi(
    const float* __restrict__ A, int M, int K,
    const float* __restrict__ W,
    const float* __restrict__ bias,
    const float* __restrict__ G1, const int* __restrict__ idx1,
    const float* __restrict__ G2, const int* __restrict__ idx2,
    const float* __restrict__ R,
    const float* __restrict__ cnt,
    int do_relu,
    float* __restrict__ Cout,
    const int* __restrict__ sidx)
{
    __shared__ float As[16][132];   // padded to avoid bank conflicts
    __shared__ float Bs[16][64];

    const int tid = threadIdx.x;
    const int bm = blockIdx.x * 128;
    const int bn = blockIdx.y * 64;
    const int tx = tid & 15;        // 16 col groups x 4 cols
    const int ty = tid >> 4;        // 16 row groups x 8 rows

    float acc[8][4];
    #pragma unroll
    for (int i = 0; i < 8; ++i)
        #pragma unroll
        for (int j = 0; j < 4; ++j) acc[i][j] = 0.f;

    for (int k0 = 0; k0 < K; k0 += 16) {
        // stage A tile 128x16 (transposed into smem)
        #pragma unroll
        for (int l = 0; l < 2; ++l) {
            int i = tid + l * 256;
            int r = i >> 2;
            int c4 = (i & 3) << 2;
            int row = bm + r;
            float4 v = make_float4(0.f, 0.f, 0.f, 0.f);
            if (row < M) v = *(const float4*)(A + (size_t)row * K + k0 + c4);
            As[c4 + 0][r] = v.x;
            As[c4 + 1][r] = v.y;
            As[c4 + 2][r] = v.z;
            As[c4 + 3][r] = v.w;
        }
        // stage W tile 16x64
        {
            int r = tid >> 4;
            int c4 = (tid & 15) << 2;
            *(float4*)&Bs[r][c4] = *(const float4*)(W + (size_t)(k0 + r) * HD + bn + c4);
        }
        __syncthreads();

        #pragma unroll
        for (int kk = 0; kk < 16; ++kk) {
            float4 a0 = *(const float4*)&As[kk][ty * 8];
            float4 a1 = *(const float4*)&As[kk][ty * 8 + 4];
            float4 b  = *(const float4*)&Bs[kk][tx * 4];
            float av[8] = {a0.x, a0.y, a0.z, a0.w, a1.x, a1.y, a1.z, a1.w};
            float bv[4] = {b.x, b.y, b.z, b.w};
            #pragma unroll
            for (int i = 0; i < 8; ++i)
                #pragma unroll
                for (int j = 0; j < 4; ++j)
                    acc[i][j] += av[i] * bv[j];
        }
        __syncthreads();
    }

    const int cols = bn + tx * 4;
    float4 bv4 = make_float4(0.f, 0.f, 0.f, 0.f);
    if (bias) bv4 = *(const float4*)(bias + cols);

    #pragma unroll
    for (int i = 0; i < 8; ++i) {
        int row = bm + ty * 8 + i;
        if (row >= M) continue;
        float rs = 1.f;
        if (cnt) rs = 1.f / fmaxf(cnt[row], 1.f);
        float c0 = acc[i][0] * rs + bv4.x;
        float c1 = acc[i][1] * rs + bv4.y;
        float c2 = acc[i][2] * rs + bv4.z;
        float c3 = acc[i][3] * rs + bv4.w;
        if (G1) {
            float4 g = *(const float4*)(G1 + (size_t)idx1[row] * HD + cols);
            c0 += g.x; c1 += g.y; c2 += g.z; c3 += g.w;
        }
        if (G2) {
            float4 g = *(const float4*)(G2 + (size_t)idx2[row] * HD + cols);
            c0 += g.x; c1 += g.y; c2 += g.z; c3 += g.w;
        }
        if (R) {
            float4 r4 = *(const float4*)(R + (size_t)row * HD + cols);
            c0 += r4.x; c1 += r4.y; c2 += r4.z; c3 += r4.w;
        }
        if (do_relu) {
            c0 = fmaxf(c0, 0.f); c1 = fmaxf(c1, 0.f);
            c2 = fmaxf(c2, 0.f); c3 = fmaxf(c3, 0.f);
        }
        if (sidx) {
            float* o = Cout + (size_t)sidx[row] * HD + cols;
            atomicAdd(o + 0, c0);
            atomicAdd(o + 1, c1);
            atomicAdd(o + 2, c2);
            atomicAdd(o + 3, c3);
        } else {
            *(float4*)(Cout + (size_t)row * HD + cols) = make_float4(c0, c1, c2, c3);
        }
    }
}

// ---------------- final head reduction: out[e] = h[e] . p_w2 + p_b2 ----------------
__global__ __launch_bounds__(256) void head_kernel(
    const float* __restrict__ w2, const float* __restrict__ b2,
    float* __restrict__ out)
{
    int g = blockIdx.x * blockDim.x + threadIdx.x;
    int e = g >> 5, lane = g & 31;
    if (e >= NE) return;
    const float* hr = g_eh + (size_t)e * HD;
    float acc = 0.f;
    #pragma unroll
    for (int n = lane; n < HD; n += 32) acc += hr[n] * w2[n];
    #pragma unroll
    for (int o = 16; o; o >>= 1) acc += __shfl_xor_sync(0xffffffffu, acc, o);
    if (lane == 0) out[e] = acc + b2[0];
}

// ---------------- host-side GEMM wrapper ----------------
static void gemm(const float* A, int M, int K, const float* W, const float* bias,
                 const float* G1, const int* i1, const float* G2, const int* i2,
                 const float* R, const float* cnt, int relu,
                 float* C, const int* sidx)
{
    dim3 grid((M + 127) / 128, HD / 64);
    gemm_epi<<<grid, 256>>>(A, M, K, W, bias, G1, i1, G2, i2, R, cnt, relu, C, sidx);
}

extern "C" void kernel_launch(void* const* d_in, const int* in_sizes, int n_in,
                              void* d_out, int out_size)
{
    const float* x      = (const float*)d_in[0];
    const unsigned int* ei = (const unsigned int*)d_in[1];
    const float* eattr  = (const float*)d_in[2];
    const float* e_w1_0 = (const float*)d_in[3];
    const float* e_b1_0 = (const float*)d_in[4];
    const float* e_w2_0 = (const float*)d_in[5];
    const float* e_b2_0 = (const float*)d_in[6];
    const float* n_wm_0 = (const float*)d_in[7];
    const float* n_bm_0 = (const float*)d_in[8];
    const float* n_w1_0 = (const float*)d_in[9];
    const float* n_b1_0 = (const float*)d_in[10];
    const float* n_w2_0 = (const float*)d_in[11];
    const float* n_b2_0 = (const float*)d_in[12];
    const float* e_w1_1 = (const float*)d_in[13];
    const float* e_b1_1 = (const float*)d_in[14];
    const float* e_w2_1 = (const float*)d_in[15];
    const float* e_b2_1 = (const float*)d_in[16];
    // d_in[17..22]: layer-1 node model weights — provably dead (output uses only ea2)
    const float* p_w1   = (const float*)d_in[23];
    const float* p_b1   = (const float*)d_in[24];
    const float* p_w2   = (const float*)d_in[25];
    const float* p_b2   = (const float*)d_in[26];
    float* out = (float*)d_out;

    float *PA, *PB, *PMX, *XW, *S, *CNT, *NH, *X2, *EH, *EA1, *EA2;
    int *SRC, *DST;
    cudaGetSymbolAddress((void**)&PA,  g_PA);
    cudaGetSymbolAddress((void**)&PB,  g_PB);
    cudaGetSymbolAddress((void**)&PMX, g_PMX);
    cudaGetSymbolAddress((void**)&XW,  g_XW);
    cudaGetSymbolAddress((void**)&S,   g_s);
    cudaGetSymbolAddress((void**)&CNT, g_cnt);
    cudaGetSymbolAddress((void**)&NH,  g_nh);
    cudaGetSymbolAddress((void**)&X2,  g_x2);
    cudaGetSymbolAddress((void**)&EH,  g_eh);
    cudaGetSymbolAddress((void**)&EA1, g_ea1);
    cudaGetSymbolAddress((void**)&EA2, g_ea2);
    cudaGetSymbolAddress((void**)&SRC, g_src);
    cudaGetSymbolAddress((void**)&DST, g_dst);

    // weight sub-blocks (concat factorization; all row-major with 256 cols)
    const float* Wxi0 = e_w1_0;                 // x_i part  [512,256]
    const float* Wxj0 = e_w1_0 + 512 * 256;     // x_j part  [512,256]
    const float* Wea0 = e_w1_0 + 1024 * 256;    // ea  part  [6,256]
    const float* Wmx0 = n_wm_0;                 // x_i part  [512,256]
    const float* Wme0 = n_wm_0 + 512 * 256;     // ea  part  [256,256]
    const float* W1x0 = n_w1_0;                 // x   part  [512,256]
    const float* W1s0 = n_w1_0 + 512 * 256;     // s   part  [256,256]
    const float* Wxi1 = e_w1_1;                 // [256,256]
    const float* Wxj1 = e_w1_1 + 256 * 256;     // [256,256]
    const float* Wea1 = e_w1_1 + 512 * 256;     // [256,256]

    // 1) indices + degree
    convert_idx<<<(NE + 255) / 256, 256>>>(ei);
    zero_s_cnt<<<(NN * HD + 255) / 256, 256>>>();
    deg_kernel<<<(NE + 255) / 256, 256>>>();

    // 2) node-level projections for layer 0
    gemm(x, NN, 512, Wxi0, nullptr, nullptr, nullptr, nullptr, nullptr, nullptr, nullptr, 0, PA,  nullptr);
    gemm(x, NN, 512, Wxj0, nullptr, nullptr, nullptr, nullptr, nullptr, nullptr, nullptr, 0, PB,  nullptr);
    gemm(x, NN, 512, Wmx0, nullptr, nullptr, nullptr, nullptr, nullptr, nullptr, nullptr, 0, PMX, nullptr);
    gemm(x, NN, 512, W1x0, nullptr, nullptr, nullptr, nullptr, nullptr, nullptr, nullptr, 0, XW,  nullptr);

    // 3) eh0 = relu(PA[src] + PB[dst] + ea@Wea0 + e_b1_0)
    assemble_eh0<<<NE / 64, 256>>>(eattr, Wea0, e_b1_0);

    // 4) ea1 = eh0 @ e_w2_0 + e_b2_0
    gemm(EH, NE, 256, e_w2_0, e_b2_0, nullptr, nullptr, nullptr, nullptr, nullptr, nullptr, 0, EA1, nullptr);

    // 5) msg0 = relu(PMX[src] + ea1@Wme0 + n_bm_0); scatter-add into s[dst]
    gemm(EA1, NE, 256, Wme0, n_bm_0, PMX, SRC, nullptr, nullptr, nullptr, nullptr, 1, S, DST);

    // 6) nh0 = relu((s/max(cnt,1))@W1s0 + XW + n_b1_0)   (mean folded as rowscale)
    gemm(S, NN, 256, W1s0, n_b1_0, nullptr, nullptr, nullptr, nullptr, XW, CNT, 1, NH, nullptr);

    // 7) x2 = nh0 @ n_w2_0 + n_b2_0
    gemm(NH, NN, 256, n_w2_0, n_b2_0, nullptr, nullptr, nullptr, nullptr, nullptr, nullptr, 0, X2, nullptr);

    // 8) node-level projections for layer-1 edge model (reuse PA/PB)
    gemm(X2, NN, 256, Wxi1, nullptr, nullptr, nullptr, nullptr, nullptr, nullptr, nullptr, 0, PA, nullptr);
    gemm(X2, NN, 256, Wxj1, nullptr, nullptr, nullptr, nullptr, nullptr, nullptr, nullptr, 0, PB, nullptr);

    // 9) eh1 = relu(ea1@Wea1 + e_b1_1 + PA[src] + PB[dst])    (reuse EH)
    gemm(EA1, NE, 256, Wea1, e_b1_1, PA, SRC, PB, DST, nullptr, nullptr, 1, EH, nullptr);

    // 10) ea2 = eh1 @ e_w2_1 + e_b2_1 + ea1   (residual)
    gemm(EH, NE, 256, e_w2_1, e_b2_1, nullptr, nullptr, nullptr, nullptr, EA1, nullptr, 0, EA2, nullptr);

    // 11) h = relu(ea2 @ p_w1 + p_b1)          (reuse EH)
    gemm(EA2, NE, 256, p_w1, p_b1, nullptr, nullptr, nullptr, nullptr, nullptr, nullptr, 1, EH, nullptr);

    // 12) out[e] = h[e] . p_w2 + p_b2
    head_kernel<<<(NE * 32 + 255) / 256, 256>>>(p_w2, p_b2, out);

    (void)in_sizes; (void)n_in; (void)out_size;
}

// round 4
// speedup vs baseline: 1.5569x; 1.5566x over previous
#include <cuda_runtime.h>
#include <cuda_bf16.h>
#include <cstdint>

typedef __nv_bfloat16 bf16;
typedef unsigned int u32;
typedef unsigned long long u64;

#define NN 10000
#define NE 160000

// ---------------- scratch (device globals; no runtime allocation) ----------------
__device__ bf16 g_Xhi[(size_t)NN*512];
__device__ bf16 g_Xlo[(size_t)NN*512];
__device__ bf16 g_Whi[1114112];
__device__ bf16 g_Wlo[1114112];
__device__ float g_PA [(size_t)NN*256];
__device__ float g_PB [(size_t)NN*256];
__device__ float g_PMX[(size_t)NN*256];
__device__ float g_XW [(size_t)NN*256];
__device__ float g_S  [(size_t)NN*256];
__device__ float g_cnt[NN];
__device__ bf16 g_Shi [(size_t)NN*256];  __device__ bf16 g_Slo [(size_t)NN*256];
__device__ bf16 g_NHhi[(size_t)NN*256];  __device__ bf16 g_NHlo[(size_t)NN*256];
__device__ bf16 g_X2hi[(size_t)NN*256];  __device__ bf16 g_X2lo[(size_t)NN*256];
__device__ bf16 g_EHhi[(size_t)NE*256];  __device__ bf16 g_EHlo[(size_t)NE*256];
__device__ bf16 g_E1hi[(size_t)NE*256];  __device__ bf16 g_E1lo[(size_t)NE*256];
__device__ bf16 g_E2hi[(size_t)NE*256];  __device__ bf16 g_E2lo[(size_t)NE*256];
__device__ int g_src[NE];
__device__ int g_dst[NE];

// ---------------- helpers ----------------
__device__ __forceinline__ u32 smem_u32(const void* p) { return (u32)__cvta_generic_to_shared(p); }

__device__ __forceinline__ void cp16(u32 dst, const void* src, bool pred) {
    int sz = pred ? 16 : 0;
    asm volatile("cp.async.cg.shared.global [%0], [%1], 16, %2;\n" :: "r"(dst), "l"(src), "r"(sz));
}
__device__ __forceinline__ void cp_commit() { asm volatile("cp.async.commit_group;" ::: "memory"); }
template <int N> __device__ __forceinline__ void cp_wait() {
    asm volatile("cp.async.wait_group %0;" :: "n"(N) : "memory");
}

#define MMA(c, a, b0, b1)                                                      \
    asm volatile("mma.sync.aligned.m16n8k16.row.col.f32.bf16.bf16.f32 "        \
        "{%0,%1,%2,%3}, {%4,%5,%6,%7}, {%8,%9}, {%0,%1,%2,%3};"                \
        : "+f"((c)[0]), "+f"((c)[1]), "+f"((c)[2]), "+f"((c)[3])               \
        : "r"((a)[0]), "r"((a)[1]), "r"((a)[2]), "r"((a)[3]), "r"(b0), "r"(b1))

struct P2 { u32 h, l; };
__device__ __forceinline__ P2 pk2(float a, float b) {
    bf16 ha = __float2bfloat16(a), hb = __float2bfloat16(b);
    bf16 la = __float2bfloat16(a - __bfloat162float(ha));
    bf16 lb = __float2bfloat16(b - __bfloat162float(hb));
    P2 r;
    r.h = (u32)__bfloat16_as_ushort(ha) | ((u32)__bfloat16_as_ushort(hb) << 16);
    r.l = (u32)__bfloat16_as_ushort(la) | ((u32)__bfloat16_as_ushort(lb) << 16);
    return r;
}
__device__ __forceinline__ float2 b2f(u32 u) {
    float2 f;
    f.x = __uint_as_float(u << 16);
    f.y = __uint_as_float(u & 0xFFFF0000u);
    return f;
}

// ---------------- mma.sync split-bf16 GEMM with fused epilogue ----------------
// C[m, colblock] = Ahi@Bhi^T + Ahi@Blo^T + Alo@Bhi^T   (B stored [N,K] row-major)
// Block: 128 rows x 128 cols (grid.y=2), BK=32, 8 warps (4m x 2n), warp 32x64.
#define ASTRIDE 40           // smem row stride in bf16 elems (80 B)
#define AHALF   10240u       // bytes per (128 x ASTRIDE) bf16 plane
#define STAGE   40960u       // Ahi | Alo | Bhi | Blo
#define SMEM_DYN (2 * 40960)

__global__ __launch_bounds__(256)
void gemm_mma(const bf16* __restrict__ Ahi, const bf16* __restrict__ Alo, int M, int K,
              const bf16* __restrict__ Bhi, const bf16* __restrict__ Blo,
              const float* __restrict__ bias,
              const float* __restrict__ G1, const int* __restrict__ idx1,
              const float* __restrict__ G2, const int* __restrict__ idx2,
              const float* __restrict__ Rf,
              const bf16* __restrict__ Rh, const bf16* __restrict__ Rl,
              int do_relu,
              float* __restrict__ outF, bf16* __restrict__ outHi, bf16* __restrict__ outLo,
              const int* __restrict__ sidx, float* __restrict__ sbuf,
              const float* __restrict__ dotW, float* __restrict__ dotO)
{
    extern __shared__ char dyn[];
    const int tid = threadIdx.x;
    const int wid = tid >> 5, lid = tid & 31;
    const int g = lid >> 2, tg = lid & 3;
    const int wm = (wid & 3) * 32;          // warp m offset in block
    const int wn = (wid >> 2) * 64;         // warp n offset in block
    const int bm = blockIdx.x * 128;
    const int bn = blockIdx.y * 128;        // global col base of block
    const int NC = K >> 5;

    float acc[2][8][4];
    #pragma unroll
    for (int mt = 0; mt < 2; ++mt)
        #pragma unroll
        for (int nt = 0; nt < 8; ++nt)
            #pragma unroll
            for (int q = 0; q < 4; ++q) acc[mt][nt][q] = 0.f;

    auto ld_stage = [&](int c) {
        u32 st = smem_u32(dyn) + (u32)(c & 1) * STAGE;
        int k0 = c << 5;
        #pragma unroll
        for (int it = 0; it < 2; ++it) {
            int slot = tid + it * 256;
            int r = slot >> 2, j = slot & 3;
            u32 so = st + (u32)(r * 80 + j * 16);
            bool p = (bm + r) < M;
            cp16(so,               (const char*)(Ahi + (size_t)(bm + r) * K + k0) + j * 16, p);
            cp16(so + AHALF,       (const char*)(Alo + (size_t)(bm + r) * K + k0) + j * 16, p);
            cp16(so + 2u * AHALF,  (const char*)(Bhi + (size_t)(bn + r) * K + k0) + j * 16, true);
            cp16(so + 3u * AHALF,  (const char*)(Blo + (size_t)(bn + r) * K + k0) + j * 16, true);
        }
        cp_commit();
    };

    ld_stage(0);
    for (int c = 0; c < NC; ++c) {
        if (c + 1 < NC) { ld_stage(c + 1); cp_wait<1>(); }
        else            { cp_wait<0>(); }
        __syncthreads();
        const char* st = dyn + (size_t)(c & 1) * STAGE;
        const bf16* Ah = (const bf16*)st;
        const bf16* Al = (const bf16*)(st + AHALF);
        const bf16* Bh = (const bf16*)(st + 2u * AHALF);
        const bf16* Bl = (const bf16*)(st + 3u * AHALF);
        #pragma unroll
        for (int kk = 0; kk < 32; kk += 16) {
            u32 ah[2][4], al[2][4];
            #pragma unroll
            for (int mt = 0; mt < 2; ++mt) {
                int e0 = (wm + mt * 16 + g) * ASTRIDE + kk + tg * 2;
                int e1 = e0 + 8 * ASTRIDE;
                ah[mt][0] = *(const u32*)(Ah + e0);
                ah[mt][1] = *(const u32*)(Ah + e1);
                ah[mt][2] = *(const u32*)(Ah + e0 + 8);
                ah[mt][3] = *(const u32*)(Ah + e1 + 8);
                al[mt][0] = *(const u32*)(Al + e0);
                al[mt][1] = *(const u32*)(Al + e1);
                al[mt][2] = *(const u32*)(Al + e0 + 8);
                al[mt][3] = *(const u32*)(Al + e1 + 8);
            }
            #pragma unroll
            for (int nt = 0; nt < 8; ++nt) {
                int e = (wn + nt * 8 + g) * ASTRIDE + kk + tg * 2;
                u32 bh0 = *(const u32*)(Bh + e), bh1 = *(const u32*)(Bh + e + 8);
                u32 bl0 = *(const u32*)(Bl + e), bl1 = *(const u32*)(Bl + e + 8);
                #pragma unroll
                for (int mt = 0; mt < 2; ++mt) {
                    MMA(acc[mt][nt], ah[mt], bh0, bh1);
                    MMA(acc[mt][nt], ah[mt], bl0, bl1);
                    MMA(acc[mt][nt], al[mt], bh0, bh1);
                }
            }
        }
        __syncthreads();
    }

    // ---- epilogue ----
    const int colbase = bn + wn + tg * 2;   // global col of pair 0; pairs at +8*nt
    float2 bi[8];
    #pragma unroll
    for (int nt = 0; nt < 8; ++nt)
        bi[nt] = bias ? *(const float2*)(bias + colbase + nt * 8) : make_float2(0.f, 0.f);

    #pragma unroll
    for (int mt = 0; mt < 2; ++mt)
    #pragma unroll
    for (int rr = 0; rr < 2; ++rr) {
        const int row = bm + wm + mt * 16 + g + rr * 8;
        const bool rok = row < M;
        float cc[16];
        #pragma unroll
        for (int nt = 0; nt < 8; ++nt) {
            cc[nt * 2]     = acc[mt][nt][rr * 2]     + bi[nt].x;
            cc[nt * 2 + 1] = acc[mt][nt][rr * 2 + 1] + bi[nt].y;
        }
        if (G1 && rok) {
            const float* gb = G1 + (size_t)idx1[row] * 256;
            #pragma unroll
            for (int nt = 0; nt < 8; ++nt) {
                float2 v = *(const float2*)(gb + colbase + nt * 8);
                cc[nt * 2] += v.x; cc[nt * 2 + 1] += v.y;
            }
        }
        if (G2 && rok) {
            const float* gb = G2 + (size_t)idx2[row] * 256;
            #pragma unroll
            for (int nt = 0; nt < 8; ++nt) {
                float2 v = *(const float2*)(gb + colbase + nt * 8);
                cc[nt * 2] += v.x; cc[nt * 2 + 1] += v.y;
            }
        }
        if (Rf && rok) {
            const float* gb = Rf + (size_t)row * 256;
            #pragma unroll
            for (int nt = 0; nt < 8; ++nt) {
                float2 v = *(const float2*)(gb + colbase + nt * 8);
                cc[nt * 2] += v.x; cc[nt * 2 + 1] += v.y;
            }
        }
        if (Rh && rok) {
            const bf16* gh = Rh + (size_t)row * 256;
            const bf16* gl = Rl + (size_t)row * 256;
            #pragma unroll
            for (int nt = 0; nt < 8; ++nt) {
                float2 fh = b2f(*(const u32*)(gh + colbase + nt * 8));
                float2 fl = b2f(*(const u32*)(gl + colbase + nt * 8));
                cc[nt * 2]     += fh.x + fl.x;
                cc[nt * 2 + 1] += fh.y + fl.y;
            }
        }
        if (do_relu) {
            #pragma unroll
            for (int j = 0; j < 16; ++j) cc[j] = fmaxf(cc[j], 0.f);
        }
        if (dotW) {
            float p = 0.f;
            #pragma unroll
            for (int nt = 0; nt < 8; ++nt) {
                float2 w = *(const float2*)(dotW + colbase + nt * 8);
                p += cc[nt * 2] * w.x + cc[nt * 2 + 1] * w.y;
            }
            p += __shfl_xor_sync(0xffffffffu, p, 1);
            p += __shfl_xor_sync(0xffffffffu, p, 2);
            if (tg == 0 && rok) atomicAdd(dotO + row, p);
        }
        if (outF && rok) {
            float* ob = outF + (size_t)row * 256;
            #pragma unroll
            for (int nt = 0; nt < 8; ++nt)
                *(float2*)(ob + colbase + nt * 8) = make_float2(cc[nt * 2], cc[nt * 2 + 1]);
        }
        if (outHi && rok) {
            bf16* oh = outHi + (size_t)row * 256;
            bf16* ol = outLo + (size_t)row * 256;
            #pragma unroll
            for (int nt = 0; nt < 8; ++nt) {
                P2 p = pk2(cc[nt * 2], cc[nt * 2 + 1]);
                *(u32*)(oh + colbase + nt * 8) = p.h;
                *(u32*)(ol + colbase + nt * 8) = p.l;
            }
        }
        if (sidx && rok) {
            float* sb = sbuf + (size_t)sidx[row] * 256;
            #pragma unroll
            for (int nt = 0; nt < 8; ++nt) {
                atomicAdd(sb + colbase + nt * 8,     cc[nt * 2]);
                atomicAdd(sb + colbase + nt * 8 + 1, cc[nt * 2 + 1]);
            }
        }
    }
}

// ---------------- utility kernels ----------------
__global__ void convert_idx(const unsigned int* __restrict__ raw) {
    __shared__ int s64;
    if (threadIdx.x == 0) {
        int ok = 1;
        for (int i = 1; i < 256; i += 2) if (raw[i] != 0u) { ok = 0; break; }
        s64 = ok;
    }
    __syncthreads();
    int i = blockIdx.x * blockDim.x + threadIdx.x;
    if (i < NE) {
        if (s64) { g_src[i] = (int)raw[2*(size_t)i]; g_dst[i] = (int)raw[2*((size_t)NE + i)]; }
        else { const int* r32 = (const int*)raw; g_src[i] = r32[i]; g_dst[i] = r32[NE + i]; }
    }
}
__global__ void zero_s_cnt() {
    size_t i = (size_t)blockIdx.x * blockDim.x + threadIdx.x;
    if (i < (size_t)NN * 256) g_S[i] = 0.f;
    if (i < NN) g_cnt[i] = 0.f;
}
__global__ void deg_kernel() {
    int i = blockIdx.x * blockDim.x + threadIdx.x;
    if (i < NE) atomicAdd(&g_cnt[g_dst[i]], 1.0f);
}
__global__ void xsplit(const float* __restrict__ x) {
    size_t i = (size_t)blockIdx.x * blockDim.x + threadIdx.x;
    if (i < (size_t)NN * 512) {
        float v = x[i];
        bf16 h = __float2bfloat16(v);
        g_Xhi[i] = h;
        g_Xlo[i] = __float2bfloat16(v - __bfloat162float(h));
    }
}
__global__ void wsplit_t(const float* __restrict__ W, int K, bf16* __restrict__ hi, bf16* __restrict__ lo) {
    int i = blockIdx.x * 256 + threadIdx.x;
    if (i >= 256 * K) return;
    int n = i / K, k = i - n * K;
    float v = W[(size_t)k * 256 + n];
    bf16 h = __float2bfloat16(v);
    hi[i] = h;
    lo[i] = __float2bfloat16(v - __bfloat162float(h));
}
__global__ __launch_bounds__(256) void assemble_eh0(
    const float* __restrict__ eattr, const float* __restrict__ Wea, const float* __restrict__ b1)
{
    __shared__ float Ws[6 * 256];
    __shared__ float bs[256];
    const int n = threadIdx.x;
    for (int i = n; i < 6 * 256; i += 256) Ws[i] = Wea[i];
    bs[n] = b1[n];
    __syncthreads();
    const int e0 = blockIdx.x * 64;
    for (int e = e0; e < e0 + 64; ++e) {
        const int s = g_src[e], d = g_dst[e];
        const float* ar = eattr + (size_t)e * 6;
        float t = bs[n] + g_PA[(size_t)s * 256 + n] + g_PB[(size_t)d * 256 + n];
        #pragma unroll
        for (int k = 0; k < 6; ++k) t += ar[k] * Ws[k * 256 + n];
        t = fmaxf(t, 0.f);
        bf16 h = __float2bfloat16(t);
        g_EHhi[(size_t)e * 256 + n] = h;
        g_EHlo[(size_t)e * 256 + n] = __float2bfloat16(t - __bfloat162float(h));
    }
}
__global__ void s_convert() {
    size_t i = (size_t)blockIdx.x * blockDim.x + threadIdx.x;
    if (i < (size_t)NN * 256) {
        float v = g_S[i] / fmaxf(g_cnt[i >> 8], 1.f);
        bf16 h = __float2bfloat16(v);
        g_Shi[i] = h;
        g_Slo[i] = __float2bfloat16(v - __bfloat162float(h));
    }
}
__global__ void init_out(float* __restrict__ out, const float* __restrict__ b2) {
    int i = blockIdx.x * blockDim.x + threadIdx.x;
    if (i < NE) out[i] = b2[0];
}

// ---------------- host ----------------
static void G(const bf16* Ahi, const bf16* Alo, int M, int K,
              const bf16* Bh, const bf16* Bl, const float* bias,
              const float* G1, const int* i1, const float* G2, const int* i2,
              const float* Rf, const bf16* Rh, const bf16* Rl, int relu,
              float* oF, bf16* oH, bf16* oL, const int* sidx, float* sbuf,
              const float* dW, float* dO)
{
    dim3 grid((M + 127) / 128, 2);
    gemm_mma<<<grid, 256, SMEM_DYN>>>(Ahi, Alo, M, K, Bh, Bl, bias,
        G1, i1, G2, i2, Rf, Rh, Rl, relu, oF, oH, oL, sidx, sbuf, dW, dO);
}

extern "C" void kernel_launch(void* const* d_in, const int* in_sizes, int n_in,
                              void* d_out, int out_size)
{
    const float* x      = (const float*)d_in[0];
    const unsigned int* ei = (const unsigned int*)d_in[1];
    const float* eattr  = (const float*)d_in[2];
    const float* e_w1_0 = (const float*)d_in[3];
    const float* e_b1_0 = (const float*)d_in[4];
    const float* e_w2_0 = (const float*)d_in[5];
    const float* e_b2_0 = (const float*)d_in[6];
    const float* n_wm_0 = (const float*)d_in[7];
    const float* n_bm_0 = (const float*)d_in[8];
    const float* n_w1_0 = (const float*)d_in[9];
    const float* n_b1_0 = (const float*)d_in[10];
    const float* n_w2_0 = (const float*)d_in[11];
    const float* n_b2_0 = (const float*)d_in[12];
    const float* e_w1_1 = (const float*)d_in[13];
    const float* e_b1_1 = (const float*)d_in[14];
    const float* e_w2_1 = (const float*)d_in[15];
    const float* e_b2_1 = (const float*)d_in[16];
    // d_in[17..22]: layer-1 node model — dead (output depends only on ea2)
    const float* p_w1   = (const float*)d_in[23];
    const float* p_b1   = (const float*)d_in[24];
    const float* p_w2   = (const float*)d_in[25];
    const float* p_b2   = (const float*)d_in[26];
    float* out = (float*)d_out;

    cudaFuncSetAttribute(gemm_mma, cudaFuncAttributeMaxDynamicSharedMemorySize, SMEM_DYN);

    bf16 *Xhi,*Xlo,*Whi,*Wlo,*Shi,*Slo,*NHhi,*NHlo,*X2hi,*X2lo,*EHhi,*EHlo,*E1hi,*E1lo,*E2hi,*E2lo;
    float *PA,*PB,*PMX,*XW,*S;
    int *SRC,*DST;
    cudaGetSymbolAddress((void**)&Xhi,g_Xhi);   cudaGetSymbolAddress((void**)&Xlo,g_Xlo);
    cudaGetSymbolAddress((void**)&Whi,g_Whi);   cudaGetSymbolAddress((void**)&Wlo,g_Wlo);
    cudaGetSymbolAddress((void**)&PA,g_PA);     cudaGetSymbolAddress((void**)&PB,g_PB);
    cudaGetSymbolAddress((void**)&PMX,g_PMX);   cudaGetSymbolAddress((void**)&XW,g_XW);
    cudaGetSymbolAddress((void**)&S,g_S);
    cudaGetSymbolAddress((void**)&Shi,g_Shi);   cudaGetSymbolAddress((void**)&Slo,g_Slo);
    cudaGetSymbolAddress((void**)&NHhi,g_NHhi); cudaGetSymbolAddress((void**)&NHlo,g_NHlo);
    cudaGetSymbolAddress((void**)&X2hi,g_X2hi); cudaGetSymbolAddress((void**)&X2lo,g_X2lo);
    cudaGetSymbolAddress((void**)&EHhi,g_EHhi); cudaGetSymbolAddress((void**)&EHlo,g_EHlo);
    cudaGetSymbolAddress((void**)&E1hi,g_E1hi); cudaGetSymbolAddress((void**)&E1lo,g_E1lo);
    cudaGetSymbolAddress((void**)&E2hi,g_E2hi); cudaGetSymbolAddress((void**)&E2lo,g_E2lo);
    cudaGetSymbolAddress((void**)&SRC,g_src);   cudaGetSymbolAddress((void**)&DST,g_dst);

    struct WT { const float* src; int K; size_t off; };
    const WT wt[13] = {
        { e_w1_0,             512, 0       },   // 0 Wxi0
        { e_w1_0 + 512*256,   512, 131072  },   // 1 Wxj0
        { n_wm_0,             512, 262144  },   // 2 Wmx0
        { n_w1_0,             512, 393216  },   // 3 W1x0
        { e_w2_0,             256, 524288  },   // 4
        { n_wm_0 + 512*256,   256, 589824  },   // 5 Wme0
        { n_w1_0 + 512*256,   256, 655360  },   // 6 W1s0
        { n_w2_0,             256, 720896  },   // 7
        { e_w1_1,             256, 786432  },   // 8 Wxi1
        { e_w1_1 + 256*256,   256, 851968  },   // 9 Wxj1
        { e_w1_1 + 512*256,   256, 917504  },   // 10 Wea1
        { e_w2_1,             256, 983040  },   // 11
        { p_w1,               256, 1048576 },   // 12
    };
    const float* Wea0 = e_w1_0 + 1024 * 256;

    convert_idx<<<(NE + 255) / 256, 256>>>(ei);
    zero_s_cnt<<<(NN * 256 + 255) / 256, 256>>>();
    deg_kernel<<<(NE + 255) / 256, 256>>>();
    xsplit<<<(NN * 512 + 255) / 256, 256>>>(x);
    for (int i = 0; i < 13; ++i)
        wsplit_t<<<(256 * wt[i].K + 255) / 256, 256>>>(wt[i].src, wt[i].K, Whi + wt[i].off, Wlo + wt[i].off);

    #define WH(i) (Whi + wt[i].off)
    #define WL(i) (Wlo + wt[i].off)
    #define Z nullptr

    // node projections (K=512)
    G(Xhi,Xlo, NN,512, WH(0),WL(0), Z, Z,Z, Z,Z, Z, Z,Z, 0, PA,  Z,Z, Z,Z, Z,Z);
    G(Xhi,Xlo, NN,512, WH(1),WL(1), Z, Z,Z, Z,Z, Z, Z,Z, 0, PB,  Z,Z, Z,Z, Z,Z);
    G(Xhi,Xlo, NN,512, WH(2),WL(2), Z, Z,Z, Z,Z, Z, Z,Z, 0, PMX, Z,Z, Z,Z, Z,Z);
    G(Xhi,Xlo, NN,512, WH(3),WL(3), Z, Z,Z, Z,Z, Z, Z,Z, 0, XW,  Z,Z, Z,Z, Z,Z);
    // eh0 (bf16 pair)
    assemble_eh0<<<NE / 64, 256>>>(eattr, Wea0, e_b1_0);
    // ea1 = eh0 @ e_w2_0 + b
    G(EHhi,EHlo, NE,256, WH(4),WL(4), e_b2_0, Z,Z, Z,Z, Z, Z,Z, 0, Z, E1hi,E1lo, Z,Z, Z,Z);
    // msg = relu(ea1@Wme0 + PMX[src] + b); atomicAdd -> S[dst]
    G(E1hi,E1lo, NE,256, WH(5),WL(5), n_bm_0, PMX,SRC, Z,Z, Z, Z,Z, 1, Z, Z,Z, DST,S, Z,Z);
    // Sbf = split(S / max(cnt,1))
    s_convert<<<(NN * 256 + 255) / 256, 256>>>();
    // nh = relu(Sbf@W1s0 + XW + b)
    G(Shi,Slo, NN,256, WH(6),WL(6), n_b1_0, Z,Z, Z,Z, XW, Z,Z, 1, Z, NHhi,NHlo, Z,Z, Z,Z);
    // x2 = nh@n_w2_0 + b
    G(NHhi,NHlo, NN,256, WH(7),WL(7), n_b2_0, Z,Z, Z,Z, Z, Z,Z, 0, Z, X2hi,X2lo, Z,Z, Z,Z);
    // layer-1 node projections (reuse PA/PB)
    G(X2hi,X2lo, NN,256, WH(8),WL(8), Z, Z,Z, Z,Z, Z, Z,Z, 0, PA, Z,Z, Z,Z, Z,Z);
    G(X2hi,X2lo, NN,256, WH(9),WL(9), Z, Z,Z, Z,Z, Z, Z,Z, 0, PB, Z,Z, Z,Z, Z,Z);
    // eh1 = relu(ea1@Wea1 + b + PA[src] + PB[dst])   (reuse EH)
    G(E1hi,E1lo, NE,256, WH(10),WL(10), e_b1_1, PA,SRC, PB,DST, Z, Z,Z, 1, Z, EHhi,EHlo, Z,Z, Z,Z);
    // ea2 = eh1 @ e_w2_1 + b + ea1 (residual via bf16 pair)
    G(EHhi,EHlo, NE,256, WH(11),WL(11), e_b2_1, Z,Z, Z,Z, Z, E1hi,E1lo, 0, Z, E2hi,E2lo, Z,Z, Z,Z);
    // head: out[e] = relu(ea2@p_w1 + p_b1) . p_w2 + p_b2  (fused partial-dot + atomics)
    init_out<<<(NE + 255) / 256, 256>>>(out, p_b2);
    G(E2hi,E2lo, NE,256, WH(12),WL(12), p_b1, Z,Z, Z,Z, Z, Z,Z, 1, Z, Z,Z, Z,Z, p_w2, out);

    (void)in_sizes; (void)n_in; (void)out_size;
}

// round 8
// speedup vs baseline: 1.8834x; 1.2097x over previous
#include <cuda_runtime.h>
#include <cuda_bf16.h>
#include <cstdint>

typedef __nv_bfloat16 bf16;
typedef unsigned int u32;
typedef unsigned long long u64;

#define NN 10000
#define NE 160000

// ---------------- scratch (device globals) ----------------
__device__ bf16 g_Xhi[(size_t)NN*512];
__device__ bf16 g_Xlo[(size_t)NN*512];
__device__ bf16 g_Whi[1114112];
__device__ bf16 g_Wlo[1114112];
__device__ float g_PA [(size_t)NN*256];
__device__ float g_PB [(size_t)NN*256];
__device__ float g_PMX[(size_t)NN*256];
__device__ float g_XW [(size_t)NN*256];
__device__ float g_S  [(size_t)NN*256];
__device__ float g_cnt[NN];
__device__ bf16 g_Shi [(size_t)NN*256];  __device__ bf16 g_Slo [(size_t)NN*256];
__device__ bf16 g_NHhi[(size_t)NN*256];  __device__ bf16 g_NHlo[(size_t)NN*256];
__device__ bf16 g_X2hi[(size_t)NN*256];  __device__ bf16 g_X2lo[(size_t)NN*256];
__device__ bf16 g_CAThi[(size_t)NE*512]; // [e][0:256]=eh1, [e][256:512]=eh0
__device__ bf16 g_CATlo[(size_t)NE*512];
__device__ float g_P[4*65536];           // weight products (fp32)
__device__ float g_vb[3*256];            // folded biases: msg, eh1, h
__device__ int g_src[NE];
__device__ int g_dst[NE];

// ---------------- helpers ----------------
__device__ __forceinline__ u32 smem_u32(const void* p) { return (u32)__cvta_generic_to_shared(p); }

__device__ __forceinline__ void cp16(u32 dst, const void* src, bool pred) {
    int sz = pred ? 16 : 0;
    asm volatile("cp.async.cg.shared.global [%0], [%1], 16, %2;\n" :: "r"(dst), "l"(src), "r"(sz));
}
__device__ __forceinline__ void cp_commit() { asm volatile("cp.async.commit_group;" ::: "memory"); }
template <int N> __device__ __forceinline__ void cp_wait() {
    asm volatile("cp.async.wait_group %0;" :: "n"(N) : "memory");
}

#define MMA(c, a, b0, b1)                                                      \
    asm volatile("mma.sync.aligned.m16n8k16.row.col.f32.bf16.bf16.f32 "        \
        "{%0,%1,%2,%3}, {%4,%5,%6,%7}, {%8,%9}, {%0,%1,%2,%3};"                \
        : "+f"((c)[0]), "+f"((c)[1]), "+f"((c)[2]), "+f"((c)[3])               \
        : "r"((a)[0]), "r"((a)[1]), "r"((a)[2]), "r"((a)[3]), "r"(b0), "r"(b1))

#define LDSM4(r, addr)                                                         \
    asm volatile("ldmatrix.sync.aligned.m8n8.x4.shared.b16 {%0,%1,%2,%3}, [%4];" \
        : "=r"((r)[0]), "=r"((r)[1]), "=r"((r)[2]), "=r"((r)[3]) : "r"(addr))

struct P2r { u32 h, l; };
__device__ __forceinline__ P2r pk2(float a, float b) {
    bf16 ha = __float2bfloat16(a), hb = __float2bfloat16(b);
    bf16 la = __float2bfloat16(a - __bfloat162float(ha));
    bf16 lb = __float2bfloat16(b - __bfloat162float(hb));
    P2r r;
    r.h = (u32)__bfloat16_as_ushort(ha) | ((u32)__bfloat16_as_ushort(hb) << 16);
    r.l = (u32)__bfloat16_as_ushort(la) | ((u32)__bfloat16_as_ushort(lb) << 16);
    return r;
}

// ---------------- mma.sync split-bf16 GEMM, ldmatrix mainloop ----------------
// Block 128x128 (grid.y=2), BK=32, 8 warps (4m x 2n), warp tile 32x64.
#define AHALF   10240u       // bytes per (128 x 40) bf16 plane (80B rows)
#define STAGE   40960u       // Ahi | Alo | Bhi | Blo
#define SMEM_DYN (2 * 40960)

__global__ __launch_bounds__(256)
void gemm_mma(const bf16* __restrict__ Ahi, const bf16* __restrict__ Alo, int lda, int M, int K,
              const bf16* __restrict__ Bhi, const bf16* __restrict__ Blo,
              const float* __restrict__ bias,
              const float* __restrict__ G1, const int* __restrict__ idx1,
              const float* __restrict__ G2, const int* __restrict__ idx2,
              const float* __restrict__ Rf,
              int do_relu,
              float* __restrict__ outF, bf16* __restrict__ outHi, bf16* __restrict__ outLo, int ldo,
              const int* __restrict__ sidx, float* __restrict__ sbuf,
              const float* __restrict__ dotW, float* __restrict__ dotO)
{
    extern __shared__ char dyn[];
    const int tid = threadIdx.x;
    const int wid = tid >> 5, lid = tid & 31;
    const int g = lid >> 2, tg = lid & 3;
    const int wm = (wid & 3) * 32;
    const int wn = (wid >> 2) * 64;
    const int bm = blockIdx.x * 128;
    const int bn = blockIdx.y * 128;
    const int NC = K >> 5;

    const u32 sb = smem_u32(dyn);
    // ldmatrix lane addresses (bytes within a plane)
    const u32 aoff = (u32)((wm + (lid & 15)) * 80 + ((lid >> 4) * 8) * 2);
    const u32 boff = (u32)(2u * AHALF + (wn + ((lid >> 4) & 1) * 8 + (lid & 7)) * 80
                           + (((lid >> 3) & 1) * 8) * 2);

    float acc[2][8][4];
    #pragma unroll
    for (int mt = 0; mt < 2; ++mt)
        #pragma unroll
        for (int nt = 0; nt < 8; ++nt)
            #pragma unroll
            for (int q = 0; q < 4; ++q) acc[mt][nt][q] = 0.f;

    auto ld_stage = [&](int c) {
        u32 st = sb + (u32)(c & 1) * STAGE;
        int k0 = c << 5;
        #pragma unroll
        for (int it = 0; it < 2; ++it) {
            int slot = tid + it * 256;
            int r = slot >> 2, j = slot & 3;
            u32 so = st + (u32)(r * 80 + j * 16);
            bool p = (bm + r) < M;
            cp16(so,              (const char*)(Ahi + (size_t)(bm + r) * lda + k0) + j * 16, p);
            cp16(so + AHALF,      (const char*)(Alo + (size_t)(bm + r) * lda + k0) + j * 16, p);
            cp16(so + 2u * AHALF, (const char*)(Bhi + (size_t)(bn + r) * K + k0) + j * 16, true);
            cp16(so + 3u * AHALF, (const char*)(Blo + (size_t)(bn + r) * K + k0) + j * 16, true);
        }
        cp_commit();
    };

    ld_stage(0);
    for (int c = 0; c < NC; ++c) {
        if (c + 1 < NC) { ld_stage(c + 1); cp_wait<1>(); }
        else            { cp_wait<0>(); }
        __syncthreads();
        const u32 stg = sb + (u32)(c & 1) * STAGE;
        #pragma unroll
        for (int kk = 0; kk < 32; kk += 16) {
            const u32 kb = (u32)(kk * 2);
            u32 ah[2][4], al[2][4], bh[4][4], bl[4][4];
            #pragma unroll
            for (int mt = 0; mt < 2; ++mt) {
                LDSM4(ah[mt], stg + aoff + kb + (u32)(mt * 1280));
                LDSM4(al[mt], stg + aoff + kb + (u32)(mt * 1280) + AHALF);
            }
            #pragma unroll
            for (int np = 0; np < 4; ++np) {
                LDSM4(bh[np], stg + boff + kb + (u32)(np * 1280));
                LDSM4(bl[np], stg + boff + kb + (u32)(np * 1280) + AHALF);
            }
            #pragma unroll
            for (int np = 0; np < 4; ++np)
                #pragma unroll
                for (int h = 0; h < 2; ++h) {
                    const int nt = np * 2 + h;
                    const u32 bh0 = bh[np][h*2], bh1 = bh[np][h*2+1];
                    const u32 bl0 = bl[np][h*2], bl1 = bl[np][h*2+1];
                    #pragma unroll
                    for (int mt = 0; mt < 2; ++mt) {
                        MMA(acc[mt][nt], ah[mt], bh0, bh1);
                        MMA(acc[mt][nt], ah[mt], bl0, bl1);
                        MMA(acc[mt][nt], al[mt], bh0, bh1);
                    }
                }
        }
        __syncthreads();
    }

    // ---- epilogue ----
    const int colbase = bn + wn + tg * 2;
    float2 bi[8];
    #pragma unroll
    for (int nt = 0; nt < 8; ++nt)
        bi[nt] = bias ? *(const float2*)(bias + colbase + nt * 8) : make_float2(0.f, 0.f);

    #pragma unroll
    for (int mt = 0; mt < 2; ++mt)
    #pragma unroll
    for (int rr = 0; rr < 2; ++rr) {
        const int row = bm + wm + mt * 16 + g + rr * 8;
        const bool rok = row < M;
        float cc[16];
        #pragma unroll
        for (int nt = 0; nt < 8; ++nt) {
            cc[nt*2]   = acc[mt][nt][rr*2]   + bi[nt].x;
            cc[nt*2+1] = acc[mt][nt][rr*2+1] + bi[nt].y;
        }
        if (G1 && rok) {
            const float* gb = G1 + (size_t)idx1[row] * 256;
            #pragma unroll
            for (int nt = 0; nt < 8; ++nt) {
                float2 v = *(const float2*)(gb + colbase + nt * 8);
                cc[nt*2] += v.x; cc[nt*2+1] += v.y;
            }
        }
        if (G2 && rok) {
            const float* gb = G2 + (size_t)idx2[row] * 256;
            #pragma unroll
            for (int nt = 0; nt < 8; ++nt) {
                float2 v = *(const float2*)(gb + colbase + nt * 8);
                cc[nt*2] += v.x; cc[nt*2+1] += v.y;
            }
        }
        if (Rf && rok) {
            const float* gb = Rf + (size_t)row * 256;
            #pragma unroll
            for (int nt = 0; nt < 8; ++nt) {
                float2 v = *(const float2*)(gb + colbase + nt * 8);
                cc[nt*2] += v.x; cc[nt*2+1] += v.y;
            }
        }
        if (do_relu) {
            #pragma unroll
            for (int j = 0; j < 16; ++j) cc[j] = fmaxf(cc[j], 0.f);
        }
        if (dotW) {
            float p = 0.f;
            #pragma unroll
            for (int nt = 0; nt < 8; ++nt) {
                float2 w = *(const float2*)(dotW + colbase + nt * 8);
                p += cc[nt*2] * w.x + cc[nt*2+1] * w.y;
            }
            p += __shfl_xor_sync(0xffffffffu, p, 1);
            p += __shfl_xor_sync(0xffffffffu, p, 2);
            if (tg == 0 && rok) atomicAdd(dotO + row, p);
        }
        if (outF && rok) {
            float* ob = outF + (size_t)row * 256;
            #pragma unroll
            for (int nt = 0; nt < 8; ++nt)
                *(float2*)(ob + colbase + nt * 8) = make_float2(cc[nt*2], cc[nt*2+1]);
        }
        if (outHi && rok) {
            bf16* oh = outHi + (size_t)row * ldo;
            bf16* ol = outLo + (size_t)row * ldo;
            #pragma unroll
            for (int nt = 0; nt < 8; ++nt) {
                P2r p = pk2(cc[nt*2], cc[nt*2+1]);
                *(u32*)(oh + colbase + nt * 8) = p.h;
                *(u32*)(ol + colbase + nt * 8) = p.l;
            }
        }
        if (sidx && rok) {
            float* sbp = sbuf + (size_t)sidx[row] * 256;
            #pragma unroll
            for (int nt = 0; nt < 8; ++nt) {
                atomicAdd(sbp + colbase + nt * 8,     cc[nt*2]);
                atomicAdd(sbp + colbase + nt * 8 + 1, cc[nt*2+1]);
            }
        }
    }
}

// ---------------- precompute kernels ----------------
// C[256,256] = A@B, fp32
__global__ void mm256(const float* __restrict__ A, const float* __restrict__ B, float* __restrict__ C) {
    __shared__ float As[16][16], Bs[16][17];
    int ty = threadIdx.y, tx = threadIdx.x;
    int row = blockIdx.y * 16 + ty, col = blockIdx.x * 16 + tx;
    float acc = 0.f;
    for (int t = 0; t < 16; ++t) {
        As[ty][tx] = A[row * 256 + t * 16 + tx];
        Bs[ty][tx] = B[(t * 16 + ty) * 256 + col];
        __syncthreads();
        #pragma unroll
        for (int k = 0; k < 16; ++k) acc += As[ty][k] * Bs[k][tx];
        __syncthreads();
    }
    C[row * 256 + col] = acc;
}
// out[n] = sum_k (v1[k]+v2[k]) * W[k,n] + add[n]
__global__ void vecmat(const float* __restrict__ v1, const float* __restrict__ v2,
                       const float* __restrict__ W, const float* __restrict__ add,
                       float* __restrict__ out) {
    __shared__ float vv[256];
    int n = threadIdx.x;
    vv[n] = v1[n] + (v2 ? v2[n] : 0.f);
    __syncthreads();
    float s = add[n];
    for (int k = 0; k < 256; ++k) s += vv[k] * W[k * 256 + n];
    out[n] = s;
}

// ---------------- utility kernels ----------------
__global__ void convert_idx(const unsigned int* __restrict__ raw) {
    __shared__ int s64;
    if (threadIdx.x == 0) {
        int ok = 1;
        for (int i = 1; i < 256; i += 2) if (raw[i] != 0u) { ok = 0; break; }
        s64 = ok;
    }
    __syncthreads();
    int i = blockIdx.x * blockDim.x + threadIdx.x;
    if (i < NE) {
        if (s64) { g_src[i] = (int)raw[2*(size_t)i]; g_dst[i] = (int)raw[2*((size_t)NE + i)]; }
        else { const int* r32 = (const int*)raw; g_src[i] = r32[i]; g_dst[i] = r32[NE + i]; }
    }
}
__global__ void zero_s_cnt() {
    size_t i = (size_t)blockIdx.x * blockDim.x + threadIdx.x;
    if (i < (size_t)NN * 256) g_S[i] = 0.f;
    if (i < NN) g_cnt[i] = 0.f;
}
__global__ void deg_kernel() {
    int i = blockIdx.x * blockDim.x + threadIdx.x;
    if (i < NE) atomicAdd(&g_cnt[g_dst[i]], 1.0f);
}
__global__ void xsplit(const float* __restrict__ x) {
    size_t i = (size_t)blockIdx.x * blockDim.x + threadIdx.x;
    if (i < (size_t)NN * 512) {
        float v = x[i];
        bf16 h = __float2bfloat16(v);
        g_Xhi[i] = h;
        g_Xlo[i] = __float2bfloat16(v - __bfloat162float(h));
    }
}
// transpose+split: src [K,256] fp32 -> dst[n*dstStride + dstOff + k]
__global__ void wsplit_t(const float* __restrict__ W, int K,
                         bf16* __restrict__ hi, bf16* __restrict__ lo,
                         int dstStride, int dstOff) {
    int i = blockIdx.x * 256 + threadIdx.x;
    if (i >= 256 * K) return;
    int n = i / K, k = i - n * K;
    float v = W[(size_t)k * 256 + n];
    bf16 h = __float2bfloat16(v);
    size_t d = (size_t)n * dstStride + dstOff + k;
    hi[d] = h;
    lo[d] = __float2bfloat16(v - __bfloat162float(h));
}
// eh0 -> CAT[e][256:512]
__global__ __launch_bounds__(256) void assemble_eh0(
    const float* __restrict__ eattr, const float* __restrict__ Wea, const float* __restrict__ b1)
{
    __shared__ float Ws[6 * 256];
    __shared__ float bs[256];
    const int n = threadIdx.x;
    for (int i = n; i < 6 * 256; i += 256) Ws[i] = Wea[i];
    bs[n] = b1[n];
    __syncthreads();
    const int e0 = blockIdx.x * 64;
    for (int e = e0; e < e0 + 64; ++e) {
        const int s = g_src[e], d = g_dst[e];
        const float* ar = eattr + (size_t)e * 6;
        float t = bs[n] + g_PA[(size_t)s * 256 + n] + g_PB[(size_t)d * 256 + n];
        #pragma unroll
        for (int k = 0; k < 6; ++k) t += ar[k] * Ws[k * 256 + n];
        t = fmaxf(t, 0.f);
        bf16 h = __float2bfloat16(t);
        size_t o = (size_t)e * 512 + 256 + n;
        g_CAThi[o] = h;
        g_CATlo[o] = __float2bfloat16(t - __bfloat162float(h));
    }
}
__global__ void s_convert() {
    size_t i = (size_t)blockIdx.x * blockDim.x + threadIdx.x;
    if (i < (size_t)NN * 256) {
        float v = g_S[i] / fmaxf(g_cnt[i >> 8], 1.f);
        bf16 h = __float2bfloat16(v);
        g_Shi[i] = h;
        g_Slo[i] = __float2bfloat16(v - __bfloat162float(h));
    }
}
__global__ void init_out(float* __restrict__ out, const float* __restrict__ b2) {
    int i = blockIdx.x * blockDim.x + threadIdx.x;
    if (i < NE) out[i] = b2[0];
}

// ---------------- host ----------------
static void G(const bf16* Ahi, const bf16* Alo, int lda, int M, int K,
              const bf16* Bh, const bf16* Bl, const float* bias,
              const float* G1, const int* i1, const float* G2, const int* i2,
              const float* Rf, int relu,
              float* oF, bf16* oH, bf16* oL, int ldo,
              const int* sidx, float* sbuf, const float* dW, float* dO)
{
    dim3 grid((M + 127) / 128, 2);
    gemm_mma<<<grid, 256, SMEM_DYN>>>(Ahi, Alo, lda, M, K, Bh, Bl, bias,
        G1, i1, G2, i2, Rf, relu, oF, oH, oL, ldo, sidx, sbuf, dW, dO);
}

extern "C" void kernel_launch(void* const* d_in, const int* in_sizes, int n_in,
                              void* d_out, int out_size)
{
    const float* x      = (const float*)d_in[0];
    const unsigned int* ei = (const unsigned int*)d_in[1];
    const float* eattr  = (const float*)d_in[2];
    const float* e_w1_0 = (const float*)d_in[3];
    const float* e_b1_0 = (const float*)d_in[4];
    const float* e_w2_0 = (const float*)d_in[5];
    const float* e_b2_0 = (const float*)d_in[6];
    const float* n_wm_0 = (const float*)d_in[7];
    const float* n_bm_0 = (const float*)d_in[8];
    const float* n_w1_0 = (const float*)d_in[9];
    const float* n_b1_0 = (const float*)d_in[10];
    const float* n_w2_0 = (const float*)d_in[11];
    const float* n_b2_0 = (const float*)d_in[12];
    const float* e_w1_1 = (const float*)d_in[13];
    const float* e_b1_1 = (const float*)d_in[14];
    const float* e_w2_1 = (const float*)d_in[15];
    const float* e_b2_1 = (const float*)d_in[16];
    // d_in[17..22]: layer-1 node model — dead
    const float* p_w1   = (const float*)d_in[23];
    const float* p_b1   = (const float*)d_in[24];
    const float* p_w2   = (const float*)d_in[25];
    const float* p_b2   = (const float*)d_in[26];
    float* out = (float*)d_out;

    cudaFuncSetAttribute(gemm_mma, cudaFuncAttributeMaxDynamicSharedMemorySize, SMEM_DYN);

    bf16 *Xhi,*Xlo,*Whi,*Wlo,*Shi,*Slo,*NHhi,*NHlo,*X2hi,*X2lo,*CATh,*CATl;
    float *PA,*PB,*PMX,*XW,*S,*P,*VB;
    int *SRC,*DST;
    cudaGetSymbolAddress((void**)&Xhi,g_Xhi);   cudaGetSymbolAddress((void**)&Xlo,g_Xlo);
    cudaGetSymbolAddress((void**)&Whi,g_Whi);   cudaGetSymbolAddress((void**)&Wlo,g_Wlo);
    cudaGetSymbolAddress((void**)&PA,g_PA);     cudaGetSymbolAddress((void**)&PB,g_PB);
    cudaGetSymbolAddress((void**)&PMX,g_PMX);   cudaGetSymbolAddress((void**)&XW,g_XW);
    cudaGetSymbolAddress((void**)&S,g_S);
    cudaGetSymbolAddress((void**)&Shi,g_Shi);   cudaGetSymbolAddress((void**)&Slo,g_Slo);
    cudaGetSymbolAddress((void**)&NHhi,g_NHhi); cudaGetSymbolAddress((void**)&NHlo,g_NHlo);
    cudaGetSymbolAddress((void**)&X2hi,g_X2hi); cudaGetSymbolAddress((void**)&X2lo,g_X2lo);
    cudaGetSymbolAddress((void**)&CATh,g_CAThi);cudaGetSymbolAddress((void**)&CATl,g_CATlo);
    cudaGetSymbolAddress((void**)&P,g_P);       cudaGetSymbolAddress((void**)&VB,g_vb);
    cudaGetSymbolAddress((void**)&SRC,g_src);   cudaGetSymbolAddress((void**)&DST,g_dst);

    // weight offsets in Whi/Wlo (elements)
    const size_t oXi0=0, oXj0=131072, oMx0=262144, oW1x=393216;
    const size_t oW1s=524288, oNw2=589824, oXi1=655360, oXj1=720896;
    const size_t oMsg=786432, oEh1=851968, oH=917504;   // oH: [256n][512k]
    const float* Wme0 = n_wm_0 + 512*256;
    const float* W1s0 = n_w1_0 + 512*256;
    const float* Wea1 = e_w1_1 + 512*256;
    const float* Wea0 = e_w1_0 + 1024*256;

    convert_idx<<<(NE + 255) / 256, 256>>>(ei);
    zero_s_cnt<<<(NN * 256 + 255) / 256, 256>>>();
    deg_kernel<<<(NE + 255) / 256, 256>>>();
    xsplit<<<(NN * 512 + 255) / 256, 256>>>(x);

    // node weights: transpose+split
    wsplit_t<<<512, 256>>>(e_w1_0,           512, Whi+oXi0, Wlo+oXi0, 512, 0);
    wsplit_t<<<512, 256>>>(e_w1_0 + 512*256, 512, Whi+oXj0, Wlo+oXj0, 512, 0);
    wsplit_t<<<512, 256>>>(n_wm_0,           512, Whi+oMx0, Wlo+oMx0, 512, 0);
    wsplit_t<<<512, 256>>>(n_w1_0,           512, Whi+oW1x, Wlo+oW1x, 512, 0);
    wsplit_t<<<256, 256>>>(W1s0,             256, Whi+oW1s, Wlo+oW1s, 256, 0);
    wsplit_t<<<256, 256>>>(n_w2_0,           256, Whi+oNw2, Wlo+oNw2, 256, 0);
    wsplit_t<<<256, 256>>>(e_w1_1,           256, Whi+oXi1, Wlo+oXi1, 256, 0);
    wsplit_t<<<256, 256>>>(e_w1_1 + 256*256, 256, Whi+oXj1, Wlo+oXj1, 256, 0);

    // folded weight products (fp32) + splits
    dim3 mmg(16,16), mmb(16,16);
    mm256<<<mmg, mmb>>>(e_w2_0, Wme0, P + 0*65536);      // W4@W5   (msg)
    mm256<<<mmg, mmb>>>(e_w2_0, Wea1, P + 1*65536);      // W4@W10  (eh1)
    mm256<<<mmg, mmb>>>(e_w2_1, p_w1, P + 2*65536);      // W11@W12 (h, eh1 part)
    mm256<<<mmg, mmb>>>(e_w2_0, p_w1, P + 3*65536);      // W4@W12  (h, eh0 part)
    wsplit_t<<<256, 256>>>(P + 0*65536, 256, Whi+oMsg, Wlo+oMsg, 256, 0);
    wsplit_t<<<256, 256>>>(P + 1*65536, 256, Whi+oEh1, Wlo+oEh1, 256, 0);
    wsplit_t<<<256, 256>>>(P + 2*65536, 256, Whi+oH,   Wlo+oH,   512, 0);
    wsplit_t<<<256, 256>>>(P + 3*65536, 256, Whi+oH,   Wlo+oH,   512, 256);
    // folded biases
    vecmat<<<1, 256>>>(e_b2_0, nullptr, Wme0, n_bm_0, VB + 0);     // msg
    vecmat<<<1, 256>>>(e_b2_0, nullptr, Wea1, e_b1_1, VB + 256);   // eh1
    vecmat<<<1, 256>>>(e_b2_0, e_b2_1,  p_w1, p_b1,   VB + 512);   // h

    #define Z nullptr
    // node projections (K=512)
    G(Xhi,Xlo,512, NN,512, Whi+oXi0,Wlo+oXi0, Z, Z,Z, Z,Z, Z, 0, PA,  Z,Z,0, Z,Z, Z,Z);
    G(Xhi,Xlo,512, NN,512, Whi+oXj0,Wlo+oXj0, Z, Z,Z, Z,Z, Z, 0, PB,  Z,Z,0, Z,Z, Z,Z);
    G(Xhi,Xlo,512, NN,512, Whi+oMx0,Wlo+oMx0, Z, Z,Z, Z,Z, Z, 0, PMX, Z,Z,0, Z,Z, Z,Z);
    G(Xhi,Xlo,512, NN,512, Whi+oW1x,Wlo+oW1x, Z, Z,Z, Z,Z, Z, 0, XW,  Z,Z,0, Z,Z, Z,Z);
    // eh0 -> CAT[:,256:512]
    assemble_eh0<<<NE / 64, 256>>>(eattr, Wea0, e_b1_0);
    // msg = relu(eh0@(W4@W5) + PMX[src] + vb_msg); atomicAdd -> S[dst]
    G(CATh+256,CATl+256,512, NE,256, Whi+oMsg,Wlo+oMsg, VB+0, PMX,SRC, Z,Z, Z, 1, Z, Z,Z,0, DST,S, Z,Z);
    // Sbf = split(S / max(cnt,1))
    s_convert<<<(NN * 256 + 255) / 256, 256>>>();
    // nh = relu(Sbf@W1s0 + XW + n_b1_0)
    G(Shi,Slo,256, NN,256, Whi+oW1s,Wlo+oW1s, n_b1_0, Z,Z, Z,Z, XW, 1, Z, NHhi,NHlo,256, Z,Z, Z,Z);
    // x2 = nh@n_w2_0 + n_b2_0
    G(NHhi,NHlo,256, NN,256, Whi+oNw2,Wlo+oNw2, n_b2_0, Z,Z, Z,Z, Z, 0, Z, X2hi,X2lo,256, Z,Z, Z,Z);
    // layer-1 node projections
    G(X2hi,X2lo,256, NN,256, Whi+oXi1,Wlo+oXi1, Z, Z,Z, Z,Z, Z, 0, PA, Z,Z,0, Z,Z, Z,Z);
    G(X2hi,X2lo,256, NN,256, Whi+oXj1,Wlo+oXj1, Z, Z,Z, Z,Z, Z, 0, PB, Z,Z,0, Z,Z, Z,Z);
    // eh1 = relu(eh0@(W4@W10) + PA[src] + PB[dst] + vb_eh1) -> CAT[:,0:256]
    G(CATh+256,CATl+256,512, NE,256, Whi+oEh1,Wlo+oEh1, VB+256, PA,SRC, PB,DST, Z, 1, Z, CATh,CATl,512, Z,Z, Z,Z);
    // out = relu([eh1|eh0]@Wh + vb_h) . p_w2 + p_b2
    init_out<<<(NE + 255) / 256, 256>>>(out, p_b2);
    G(CATh,CATl,512, NE,512, Whi+oH,Wlo+oH, VB+512, Z,Z, Z,Z, Z, 1, Z, Z,Z,0, Z,Z, p_w2, out);

    (void)in_sizes; (void)n_in; (void)out_size;
}

// round 17
// speedup vs baseline: 1.9996x; 1.0617x over previous
#include <cuda_runtime.h>
#include <cuda_bf16.h>
#include <cstdint>

typedef __nv_bfloat16 bf16;
typedef unsigned int u32;
typedef unsigned long long u64;

#define NN 10000
#define NE 160000

// ---------------- scratch (device globals) ----------------
__device__ bf16 g_Xhi[(size_t)NN*512];
__device__ bf16 g_Xlo[(size_t)NN*512];
__device__ bf16 g_Whi[1114112];
__device__ bf16 g_Wlo[1114112];
__device__ float g_PP [(size_t)NN*1024];  // L0: [PA|PB|PMX|XW] stride1024; later L1: [PA1|PB1] stride 512
__device__ float g_S  [(size_t)NN*256];
__device__ float g_cnt[NN];
__device__ bf16 g_Shi [(size_t)NN*256];  __device__ bf16 g_Slo [(size_t)NN*256];
__device__ bf16 g_NHhi[(size_t)NN*256];  __device__ bf16 g_NHlo[(size_t)NN*256];
__device__ bf16 g_X2hi[(size_t)NN*256];  __device__ bf16 g_X2lo[(size_t)NN*256];
__device__ bf16 g_CAThi[(size_t)NE*512]; // [e][0:256]=eh1, [e][256:512]=eh0
__device__ bf16 g_CATlo[(size_t)NE*512];
__device__ float g_P[4*65536];           // weight products (fp32)
__device__ float g_vb[3*256];            // folded biases: msg, eh1, h
__device__ int g_src[NE];
__device__ int g_dst[NE];

// ---------------- helpers ----------------
__device__ __forceinline__ u32 smem_u32(const void* p) { return (u32)__cvta_generic_to_shared(p); }

__device__ __forceinline__ void cp16(u32 dst, const void* src, bool pred) {
    int sz = pred ? 16 : 0;
    asm volatile("cp.async.cg.shared.global [%0], [%1], 16, %2;\n" :: "r"(dst), "l"(src), "r"(sz));
}
__device__ __forceinline__ void cp_commit() { asm volatile("cp.async.commit_group;" ::: "memory"); }
template <int N> __device__ __forceinline__ void cp_wait() {
    asm volatile("cp.async.wait_group %0;" :: "n"(N) : "memory");
}

#define MMA(c, a, b0, b1)                                                      \
    asm volatile("mma.sync.aligned.m16n8k16.row.col.f32.bf16.bf16.f32 "        \
        "{%0,%1,%2,%3}, {%4,%5,%6,%7}, {%8,%9}, {%0,%1,%2,%3};"                \
        : "+f"((c)[0]), "+f"((c)[1]), "+f"((c)[2]), "+f"((c)[3])               \
        : "r"((a)[0]), "r"((a)[1]), "r"((a)[2]), "r"((a)[3]), "r"(b0), "r"(b1))

#define LDSM4(r, addr)                                                         \
    asm volatile("ldmatrix.sync.aligned.m8n8.x4.shared.b16 {%0,%1,%2,%3}, [%4];" \
        : "=r"((r)[0]), "=r"((r)[1]), "=r"((r)[2]), "=r"((r)[3]) : "r"(addr))

struct P2r { u32 h, l; };
__device__ __forceinline__ P2r pk2(float a, float b) {
    bf16 ha = __float2bfloat16(a), hb = __float2bfloat16(b);
    bf16 la = __float2bfloat16(a - __bfloat162float(ha));
    bf16 lb = __float2bfloat16(b - __bfloat162float(hb));
    P2r r;
    r.h = (u32)__bfloat16_as_ushort(ha) | ((u32)__bfloat16_as_ushort(hb) << 16);
    r.l = (u32)__bfloat16_as_ushort(la) | ((u32)__bfloat16_as_ushort(lb) << 16);
    return r;
}

// ---------------- mma.sync split-bf16 GEMM, ldmatrix mainloop ----------------
// Block 128x128 (grid.y = N/128), BK=32, 8 warps (4m x 2n), warp tile 32x64.
#define AHALF   10240u       // bytes per (128 x 40) bf16 plane (80B rows)
#define STAGE   40960u       // Ahi | Alo | Bhi | Blo
#define SMEM_DYN (2 * 40960)

__global__ __launch_bounds__(256)
void gemm_mma(const bf16* __restrict__ Ahi, const bf16* __restrict__ Alo, int lda, int M, int K,
              const bf16* __restrict__ Bhi, const bf16* __restrict__ Blo,
              const float* __restrict__ bias,
              const float* __restrict__ G1, int ldg1, const int* __restrict__ idx1,
              const float* __restrict__ G2, int ldg2, const int* __restrict__ idx2,
              const float* __restrict__ Rf, int ldrf,
              int do_relu,
              float* __restrict__ outF, bf16* __restrict__ outHi, bf16* __restrict__ outLo, int ldo,
              const int* __restrict__ sidx, float* __restrict__ sbuf,
              const float* __restrict__ dotW, float* __restrict__ dotO)
{
    extern __shared__ char dyn[];
    const int tid = threadIdx.x;
    const int wid = tid >> 5, lid = tid & 31;
    const int g = lid >> 2, tg = lid & 3;
    const int wm = (wid & 3) * 32;
    const int wn = (wid >> 2) * 64;
    const int bm = blockIdx.x * 128;
    const int bn = blockIdx.y * 128;
    const int NC = K >> 5;

    const u32 sb = smem_u32(dyn);
    const u32 aoff = (u32)((wm + (lid & 15)) * 80 + ((lid >> 4) * 8) * 2);
    const u32 boff = (u32)(2u * AHALF + (wn + ((lid >> 4) & 1) * 8 + (lid & 7)) * 80
                           + (((lid >> 3) & 1) * 8) * 2);

    float acc[2][8][4];
    #pragma unroll
    for (int mt = 0; mt < 2; ++mt)
        #pragma unroll
        for (int nt = 0; nt < 8; ++nt)
            #pragma unroll
            for (int q = 0; q < 4; ++q) acc[mt][nt][q] = 0.f;

    auto ld_stage = [&](int c) {
        u32 st = sb + (u32)(c & 1) * STAGE;
        int k0 = c << 5;
        #pragma unroll
        for (int it = 0; it < 2; ++it) {
            int slot = tid + it * 256;
            int r = slot >> 2, j = slot & 3;
            u32 so = st + (u32)(r * 80 + j * 16);
            bool p = (bm + r) < M;
            cp16(so,              (const char*)(Ahi + (size_t)(bm + r) * lda + k0) + j * 16, p);
            cp16(so + AHALF,      (const char*)(Alo + (size_t)(bm + r) * lda + k0) + j * 16, p);
            cp16(so + 2u * AHALF, (const char*)(Bhi + (size_t)(bn + r) * K + k0) + j * 16, true);
            cp16(so + 3u * AHALF, (const char*)(Blo + (size_t)(bn + r) * K + k0) + j * 16, true);
        }
        cp_commit();
    };

    ld_stage(0);
    for (int c = 0; c < NC; ++c) {
        if (c + 1 < NC) { ld_stage(c + 1); cp_wait<1>(); }
        else            { cp_wait<0>(); }
        __syncthreads();
        const u32 stg = sb + (u32)(c & 1) * STAGE;
        #pragma unroll
        for (int kk = 0; kk < 32; kk += 16) {
            const u32 kb = (u32)(kk * 2);
            u32 ah[2][4], al[2][4], bh[4][4], bl[4][4];
            #pragma unroll
            for (int mt = 0; mt < 2; ++mt) {
                LDSM4(ah[mt], stg + aoff + kb + (u32)(mt * 1280));
                LDSM4(al[mt], stg + aoff + kb + (u32)(mt * 1280) + AHALF);
            }
            #pragma unroll
            for (int np = 0; np < 4; ++np) {
                LDSM4(bh[np], stg + boff + kb + (u32)(np * 1280));
                LDSM4(bl[np], stg + boff + kb + (u32)(np * 1280) + AHALF);
            }
            #pragma unroll
            for (int np = 0; np < 4; ++np)
                #pragma unroll
                for (int h = 0; h < 2; ++h) {
                    const int nt = np * 2 + h;
                    const u32 bh0 = bh[np][h*2], bh1 = bh[np][h*2+1];
                    const u32 bl0 = bl[np][h*2], bl1 = bl[np][h*2+1];
                    #pragma unroll
                    for (int mt = 0; mt < 2; ++mt) {
                        MMA(acc[mt][nt], ah[mt], bh0, bh1);
                        MMA(acc[mt][nt], ah[mt], bl0, bl1);
                        MMA(acc[mt][nt], al[mt], bh0, bh1);
                    }
                }
        }
        __syncthreads();
    }

    // ---- epilogue ----
    const int colbase = bn + wn + tg * 2;
    float2 bi[8];
    #pragma unroll
    for (int nt = 0; nt < 8; ++nt)
        bi[nt] = bias ? *(const float2*)(bias + colbase + nt * 8) : make_float2(0.f, 0.f);

    #pragma unroll
    for (int mt = 0; mt < 2; ++mt)
    #pragma unroll
    for (int rr = 0; rr < 2; ++rr) {
        const int row = bm + wm + mt * 16 + g + rr * 8;
        const bool rok = row < M;
        float cc[16];
        #pragma unroll
        for (int nt = 0; nt < 8; ++nt) {
            cc[nt*2]   = acc[mt][nt][rr*2]   + bi[nt].x;
            cc[nt*2+1] = acc[mt][nt][rr*2+1] + bi[nt].y;
        }
        if (G1 && rok) {
            const float* gb = G1 + (size_t)idx1[row] * ldg1;
            #pragma unroll
            for (int nt = 0; nt < 8; ++nt) {
                float2 v = *(const float2*)(gb + colbase + nt * 8);
                cc[nt*2] += v.x; cc[nt*2+1] += v.y;
            }
        }
        if (G2 && rok) {
            const float* gb = G2 + (size_t)idx2[row] * ldg2;
            #pragma unroll
            for (int nt = 0; nt < 8; ++nt) {
                float2 v = *(const float2*)(gb + colbase + nt * 8);
                cc[nt*2] += v.x; cc[nt*2+1] += v.y;
            }
        }
        if (Rf && rok) {
            const float* gb = Rf + (size_t)row * ldrf;
            #pragma unroll
            for (int nt = 0; nt < 8; ++nt) {
                float2 v = *(const float2*)(gb + colbase + nt * 8);
                cc[nt*2] += v.x; cc[nt*2+1] += v.y;
            }
        }
        if (do_relu) {
            #pragma unroll
            for (int j = 0; j < 16; ++j) cc[j] = fmaxf(cc[j], 0.f);
        }
        if (dotW) {
            float p = 0.f;
            #pragma unroll
            for (int nt = 0; nt < 8; ++nt) {
                float2 w = *(const float2*)(dotW + colbase + nt * 8);
                p += cc[nt*2] * w.x + cc[nt*2+1] * w.y;
            }
            p += __shfl_xor_sync(0xffffffffu, p, 1);
            p += __shfl_xor_sync(0xffffffffu, p, 2);
            if (tg == 0 && rok) atomicAdd(dotO + row, p);
        }
        if (outF && rok) {
            float* ob = outF + (size_t)row * ldo;
            #pragma unroll
            for (int nt = 0; nt < 8; ++nt)
                *(float2*)(ob + colbase + nt * 8) = make_float2(cc[nt*2], cc[nt*2+1]);
        }
        if (outHi && rok) {
            bf16* oh = outHi + (size_t)row * ldo;
            bf16* ol = outLo + (size_t)row * ldo;
            #pragma unroll
            for (int nt = 0; nt < 8; ++nt) {
                P2r p = pk2(cc[nt*2], cc[nt*2+1]);
                *(u32*)(oh + colbase + nt * 8) = p.h;
                *(u32*)(ol + colbase + nt * 8) = p.l;
            }
        }
        if (sidx && rok) {
            float* sbp = sbuf + (size_t)sidx[row] * 256;
            #pragma unroll
            for (int nt = 0; nt < 8; ++nt) {
                atomicAdd(sbp + colbase + nt * 8,     cc[nt*2]);
                atomicAdd(sbp + colbase + nt * 8 + 1, cc[nt*2+1]);
            }
        }
    }
}

// ---------------- precompute kernels ----------------
__global__ void mm256(const float* __restrict__ A, const float* __restrict__ B, float* __restrict__ C) {
    __shared__ float As[16][16], Bs[16][17];
    int ty = threadIdx.y, tx = threadIdx.x;
    int row = blockIdx.y * 16 + ty, col = blockIdx.x * 16 + tx;
    float acc = 0.f;
    for (int t = 0; t < 16; ++t) {
        As[ty][tx] = A[row * 256 + t * 16 + tx];
        Bs[ty][tx] = B[(t * 16 + ty) * 256 + col];
        __syncthreads();
        #pragma unroll
        for (int k = 0; k < 16; ++k) acc += As[ty][k] * Bs[k][tx];
        __syncthreads();
    }
    C[row * 256 + col] = acc;
}
__global__ void vecmat(const float* __restrict__ v1, const float* __restrict__ v2,
                       const float* __restrict__ W, const float* __restrict__ add,
                       float* __restrict__ out) {
    __shared__ float vv[256];
    int n = threadIdx.x;
    vv[n] = v1[n] + (v2 ? v2[n] : 0.f);
    __syncthreads();
    float s = add[n];
    for (int k = 0; k < 256; ++k) s += vv[k] * W[k * 256 + n];
    out[n] = s;
}

// ---------------- utility kernels ----------------
__global__ void convert_idx(const unsigned int* __restrict__ raw) {
    __shared__ int s64;
    if (threadIdx.x == 0) {
        int ok = 1;
        for (int i = 1; i < 256; i += 2) if (raw[i] != 0u) { ok = 0; break; }
        s64 = ok;
    }
    __syncthreads();
    int i = blockIdx.x * blockDim.x + threadIdx.x;
    if (i < NE) {
        if (s64) { g_src[i] = (int)raw[2*(size_t)i]; g_dst[i] = (int)raw[2*((size_t)NE + i)]; }
        else { const int* r32 = (const int*)raw; g_src[i] = r32[i]; g_dst[i] = r32[NE + i]; }
    }
}
__global__ void zero_s_cnt() {
    size_t i = (size_t)blockIdx.x * blockDim.x + threadIdx.x;
    if (i < (size_t)NN * 256) g_S[i] = 0.f;
    if (i < NN) g_cnt[i] = 0.f;
}
__global__ void deg_kernel() {
    int i = blockIdx.x * blockDim.x + threadIdx.x;
    if (i < NE) atomicAdd(&g_cnt[g_dst[i]], 1.0f);
}
__global__ void xsplit(const float* __restrict__ x) {
    size_t i = (size_t)blockIdx.x * blockDim.x + threadIdx.x;
    if (i < (size_t)NN * 512) {
        float v = x[i];
        bf16 h = __float2bfloat16(v);
        g_Xhi[i] = h;
        g_Xlo[i] = __float2bfloat16(v - __bfloat162float(h));
    }
}
// transpose+split: src [K,256] fp32 -> dst[n*dstStride + dstOff + k]
__global__ void wsplit_t(const float* __restrict__ W, int K,
                         bf16* __restrict__ hi, bf16* __restrict__ lo,
                         int dstStride, int dstOff) {
    int i = blockIdx.x * 256 + threadIdx.x;
    if (i >= 256 * K) return;
    int n = i / K, k = i - n * K;
    float v = W[(size_t)k * 256 + n];
    bf16 h = __float2bfloat16(v);
    size_t d = (size_t)n * dstStride + dstOff + k;
    hi[d] = h;
    lo[d] = __float2bfloat16(v - __bfloat162float(h));
}
// eh0 -> CAT[e][256:512]; reads PA=PP[:,0:256], PB=PP[:,256:512] (stride 1024)
__global__ __launch_bounds__(256) void assemble_eh0(
    const float* __restrict__ eattr, const float* __restrict__ Wea, const float* __restrict__ b1)
{
    __shared__ float Ws[6 * 256];
    __shared__ float bs[256];
    const int n = threadIdx.x;
    for (int i = n; i < 6 * 256; i += 256) Ws[i] = Wea[i];
    bs[n] = b1[n];
    __syncthreads();
    const int e0 = blockIdx.x * 64;
    for (int e = e0; e < e0 + 64; ++e) {
        const int s = g_src[e], d = g_dst[e];
        const float* ar = eattr + (size_t)e * 6;
        float t = bs[n] + g_PP[(size_t)s * 1024 + n] + g_PP[(size_t)d * 1024 + 256 + n];
        #pragma unroll
        for (int k = 0; k < 6; ++k) t += ar[k] * Ws[k * 256 + n];
        t = fmaxf(t, 0.f);
        bf16 h = __float2bfloat16(t);
        size_t o = (size_t)e * 512 + 256 + n;
        g_CAThi[o] = h;
        g_CATlo[o] = __float2bfloat16(t - __bfloat162float(h));
    }
}
__global__ void s_convert() {
    size_t i = (size_t)blockIdx.x * blockDim.x + threadIdx.x;
    if (i < (size_t)NN * 256) {
        float v = g_S[i] / fmaxf(g_cnt[i >> 8], 1.f);
        bf16 h = __float2bfloat16(v);
        g_Shi[i] = h;
        g_Slo[i] = __float2bfloat16(v - __bfloat162float(h));
    }
}
__global__ void init_out(float* __restrict__ out, const float* __restrict__ b2) {
    int i = blockIdx.x * blockDim.x + threadIdx.x;
    if (i < NE) out[i] = b2[0];
}

// ---------------- host ----------------
static void G(const bf16* Ahi, const bf16* Alo, int lda, int M, int K, int N,
              const bf16* Bh, const bf16* Bl, const float* bias,
              const float* G1, int ldg1, const int* i1,
              const float* G2, int ldg2, const int* i2,
              const float* Rf, int ldrf, int relu,
              float* oF, bf16* oH, bf16* oL, int ldo,
              const int* sidx, float* sbuf, const float* dW, float* dO)
{
    dim3 grid((M + 127) / 128, N / 128);
    gemm_mma<<<grid, 256, SMEM_DYN>>>(Ahi, Alo, lda, M, K, Bh, Bl, bias,
        G1, ldg1, i1, G2, ldg2, i2, Rf, ldrf, relu, oF, oH, oL, ldo, sidx, sbuf, dW, dO);
}

extern "C" void kernel_launch(void* const* d_in, const int* in_sizes, int n_in,
                              void* d_out, int out_size)
{
    const float* x      = (const float*)d_in[0];
    const unsigned int* ei = (const unsigned int*)d_in[1];
    const float* eattr  = (const float*)d_in[2];
    const float* e_w1_0 = (const float*)d_in[3];
    const float* e_b1_0 = (const float*)d_in[4];
    const float* e_w2_0 = (const float*)d_in[5];
    const float* e_b2_0 = (const float*)d_in[6];
    const float* n_wm_0 = (const float*)d_in[7];
    const float* n_bm_0 = (const float*)d_in[8];
    const float* n_w1_0 = (const float*)d_in[9];
    const float* n_b1_0 = (const float*)d_in[10];
    const float* n_w2_0 = (const float*)d_in[11];
    const float* n_b2_0 = (const float*)d_in[12];
    const float* e_w1_1 = (const float*)d_in[13];
    const float* e_b1_1 = (const float*)d_in[14];
    const float* e_w2_1 = (const float*)d_in[15];
    const float* e_b2_1 = (const float*)d_in[16];
    // d_in[17..22]: layer-1 node model — dead
    const float* p_w1   = (const float*)d_in[23];
    const float* p_b1   = (const float*)d_in[24];
    const float* p_w2   = (const float*)d_in[25];
    const float* p_b2   = (const float*)d_in[26];
    float* out = (float*)d_out;

    cudaFuncSetAttribute(gemm_mma, cudaFuncAttributeMaxDynamicSharedMemorySize, SMEM_DYN);

    bf16 *Xhi,*Xlo,*Whi,*Wlo,*Shi,*Slo,*NHhi,*NHlo,*X2hi,*X2lo,*CATh,*CATl;
    float *PP,*S,*P,*VB;
    int *SRC,*DST;
    cudaGetSymbolAddress((void**)&Xhi,g_Xhi);   cudaGetSymbolAddress((void**)&Xlo,g_Xlo);
    cudaGetSymbolAddress((void**)&Whi,g_Whi);   cudaGetSymbolAddress((void**)&Wlo,g_Wlo);
    cudaGetSymbolAddress((void**)&PP,g_PP);     cudaGetSymbolAddress((void**)&S,g_S);
    cudaGetSymbolAddress((void**)&Shi,g_Shi);   cudaGetSymbolAddress((void**)&Slo,g_Slo);
    cudaGetSymbolAddress((void**)&NHhi,g_NHhi); cudaGetSymbolAddress((void**)&NHlo,g_NHlo);
    cudaGetSymbolAddress((void**)&X2hi,g_X2hi); cudaGetSymbolAddress((void**)&X2lo,g_X2lo);
    cudaGetSymbolAddress((void**)&CATh,g_CAThi);cudaGetSymbolAddress((void**)&CATl,g_CATlo);
    cudaGetSymbolAddress((void**)&P,g_P);       cudaGetSymbolAddress((void**)&VB,g_vb);
    cudaGetSymbolAddress((void**)&SRC,g_src);   cudaGetSymbolAddress((void**)&DST,g_dst);

    // weight offsets in Whi/Wlo (elements)
    const size_t oNP=0;                       // [1024n][512k]  = [Wxi0|Wxj0|Wmx0|W1x0]
    const size_t oW1s=524288, oNw2=589824;    // [256n][256k]
    const size_t oP1=655360;                  // [512n][256k]   = [Wxi1|Wxj1]
    const size_t oMsg=786432, oEh1=851968;    // [256n][256k]
    const size_t oH=917504;                   // [256n][512k]
    const float* Wme0 = n_wm_0 + 512*256;
    const float* W1s0 = n_w1_0 + 512*256;
    const float* Wea1 = e_w1_1 + 512*256;
    const float* Wea0 = e_w1_0 + 1024*256;

    #define Z nullptr

    // launches 1-5: prerequisites of the big node GEMM (so launch #6 is gemm_mma for ncu -s 5)
    xsplit<<<(NN * 512 + 255) / 256, 256>>>(x);                                      // 1
    wsplit_t<<<512, 256>>>(e_w1_0,           512, Whi+oNP,          Wlo+oNP,          512, 0); // 2
    wsplit_t<<<512, 256>>>(e_w1_0 + 512*256, 512, Whi+oNP+131072,   Wlo+oNP+131072,   512, 0); // 3
    wsplit_t<<<512, 256>>>(n_wm_0,           512, Whi+oNP+262144,   Wlo+oNP+262144,   512, 0); // 4
    wsplit_t<<<512, 256>>>(n_w1_0,           512, Whi+oNP+393216,   Wlo+oNP+393216,   512, 0); // 5
    // 6: merged layer-0 node projections: PP = x @ [Wxi0|Wxj0|Wmx0|W1x0]  (N=1024)
    G(Xhi,Xlo,512, NN,512,1024, Whi+oNP,Wlo+oNP, Z, Z,0,Z, Z,0,Z, Z,0, 0, PP, Z,Z,1024, Z,Z, Z,Z);

    // remaining prep
    convert_idx<<<(NE + 255) / 256, 256>>>(ei);
    zero_s_cnt<<<(NN * 256 + 255) / 256, 256>>>();
    deg_kernel<<<(NE + 255) / 256, 256>>>();
    wsplit_t<<<256, 256>>>(W1s0,             256, Whi+oW1s, Wlo+oW1s, 256, 0);
    wsplit_t<<<256, 256>>>(n_w2_0,           256, Whi+oNw2, Wlo+oNw2, 256, 0);
    wsplit_t<<<256, 256>>>(e_w1_1,           256, Whi+oP1,        Wlo+oP1,        256, 0);
    wsplit_t<<<256, 256>>>(e_w1_1 + 256*256, 256, Whi+oP1+65536,  Wlo+oP1+65536,  256, 0);

    dim3 mmg(16,16), mmb(16,16);
    mm256<<<mmg, mmb>>>(e_w2_0, Wme0, P + 0*65536);      // W4@W5   (msg)
    mm256<<<mmg, mmb>>>(e_w2_0, Wea1, P + 1*65536);      // W4@W10  (eh1)
    mm256<<<mmg, mmb>>>(e_w2_1, p_w1, P + 2*65536);      // W11@W12 (h, eh1 part)
    mm256<<<mmg, mmb>>>(e_w2_0, p_w1, P + 3*65536);      // W4@W12  (h, eh0 part)
    wsplit_t<<<256, 256>>>(P + 0*65536, 256, Whi+oMsg, Wlo+oMsg, 256, 0);
    wsplit_t<<<256, 256>>>(P + 1*65536, 256, Whi+oEh1, Wlo+oEh1, 256, 0);
    wsplit_t<<<256, 256>>>(P + 2*65536, 256, Whi+oH,   Wlo+oH,   512, 0);
    wsplit_t<<<256, 256>>>(P + 3*65536, 256, Whi+oH,   Wlo+oH,   512, 256);
    vecmat<<<1, 256>>>(e_b2_0, nullptr, Wme0, n_bm_0, VB + 0);     // msg
    vecmat<<<1, 256>>>(e_b2_0, nullptr, Wea1, e_b1_1, VB + 256);   // eh1
    vecmat<<<1, 256>>>(e_b2_0, e_b2_1,  p_w1, p_b1,   VB + 512);   // h

    // eh0 -> CAT[:,256:512]
    assemble_eh0<<<NE / 64, 256>>>(eattr, Wea0, e_b1_0);
    // msg = relu(eh0@(W4@W5) + PMX[src] + vb_msg); atomicAdd -> S[dst]
    G(CATh+256,CATl+256,512, NE,256,256, Whi+oMsg,Wlo+oMsg, VB+0, PP+512,1024,SRC, Z,0,Z, Z,0, 1, Z, Z,Z,0, DST,S, Z,Z);
    // Sbf = split(S / max(cnt,1))
    s_convert<<<(NN * 256 + 255) / 256, 256>>>();
    // nh = relu(Sbf@W1s0 + XW + n_b1_0)
    G(Shi,Slo,256, NN,256,256, Whi+oW1s,Wlo+oW1s, n_b1_0, Z,0,Z, Z,0,Z, PP+768,1024, 1, Z, NHhi,NHlo,256, Z,Z, Z,Z);
    // x2 = nh@n_w2_0 + n_b2_0
    G(NHhi,NHlo,256, NN,256,256, Whi+oNw2,Wlo+oNw2, n_b2_0, Z,0,Z, Z,0,Z, Z,0, 0, Z, X2hi,X2lo,256, Z,Z, Z,Z);
    // merged layer-1 projections: PP[:,0:512] = x2 @ [Wxi1|Wxj1]  (stride 512, overwrites L0 data)
    G(X2hi,X2lo,256, NN,256,512, Whi+oP1,Wlo+oP1, Z, Z,0,Z, Z,0,Z, Z,0, 0, PP, Z,Z,512, Z,Z, Z,Z);
    // eh1 = relu(eh0@(W4@W10) + PA1[src] + PB1[dst] + vb_eh1) -> CAT[:,0:256]
    G(CATh+256,CATl+256,512, NE,256,256, Whi+oEh1,Wlo+oEh1, VB+256, PP,512,SRC, PP+256,512,DST, Z,0, 1, Z, CATh,CATl,512, Z,Z, Z,Z);
    // out = relu([eh1|eh0]@Wh + vb_h) . p_w2 + p_b2
    init_out<<<(NE + 255) / 256, 256>>>(out, p_b2);
    G(CATh,CATl,512, NE,512,256, Whi+oH,Wlo+oH, VB+512, Z,0,Z, Z,0,Z, Z,0, 1, Z, Z,Z,0, Z,Z, p_w2, out);

    (void)in_sizes; (void)n_in; (void)out_size;
}